// round 5
// baseline (speedup 1.0000x reference)
#include <cuda_runtime.h>
#include <cuda_bf16.h>
#include <cuda_fp16.h>
#include <cstdint>

#define D 128
#define EDGE_T 8

static constexpr int MAXN = 50000;
static constexpr int MAXE = 600000;

// Scratch (allocation-free: __device__ globals)
__device__ float g_Ah[MAXN * D];
__device__ float g_Bh[MAXN * D];
__device__ float g_Dh[MAXN * D];
__device__ float g_Eh[MAXN * D];
__device__ __half g_sig[(size_t)MAXE * D];  // sigma rows, dst-sorted, fp16
__device__ int   g_srcs[MAXE];              // src per sorted slot
__device__ int   g_cnt[MAXN];
__device__ int   g_off[MAXN];
__device__ int   g_run[MAXN];
__device__ int   g_chunk[256];
__device__ __nv_bfloat16 g_Whi[5][128 * 128];  // order: A,B,C,D,E (row-major [n][k])
__device__ __nv_bfloat16 g_Wlo[5][128 * 128];

// ---------------------------------------------------------------------------
// SMEM layout: [align 1024] Whi(32K) Wlo(32K) Ahi(32K) Alo(32K) [raw 64K edge] ctrl
// C fp32 tile (64K) overwrites Ahi/Alo after the MMA reads complete.
// ---------------------------------------------------------------------------
#define OFF_WHI 0
#define OFF_WLO 32768
#define OFF_AHI 65536
#define OFF_ALO 98304
#define OFF_CSM 65536
#define OFF_RAW 131072
#define OFF_CTRL_NODE 131072
#define OFF_CTRL_EDGE 196608
#define SMEM_NODE (1024 + OFF_CTRL_NODE + 2048)
#define SMEM_EDGE (1024 + OFF_CTRL_EDGE + 2048)

__device__ __forceinline__ uint32_t smem_u32(const void* p) {
    uint32_t a;
    asm("{ .reg .u64 t; cvta.to.shared.u64 t, %1; cvt.u32.u64 %0, t; }" : "=r"(a) : "l"(p));
    return a;
}

// bf16 tile swizzle: row-major [128][128] bf16, 256B rows, 16B-atom XOR swizzle
__device__ __forceinline__ uint32_t sw256(int r, int cbyte) {
    uint32_t o = (uint32_t)r * 256u + (uint32_t)cbyte;
    return o ^ (((uint32_t)r & 7u) << 4);
}
// fp32 tile swizzle: 512B rows
__device__ __forceinline__ uint32_t sw512(int r, int cbyte) {
    uint32_t o = (uint32_t)r * 512u + (uint32_t)cbyte;
    return o ^ (((uint32_t)r & 7u) << 4);
}

__device__ __forceinline__ void cpasync16(uint32_t dst, const void* src) {
    asm volatile("cp.async.cg.shared.global [%0], [%1], 16;" :: "r"(dst), "l"(src));
}
#define CPASYNC_COMMIT() asm volatile("cp.async.commit_group;" ::: "memory")
#define CPASYNC_WAIT0()  asm volatile("cp.async.wait_group 0;" ::: "memory")

__device__ __forceinline__ void ldm4(uint32_t addr, uint32_t r[4]) {
    asm volatile("ldmatrix.sync.aligned.m8n8.x4.shared.b16 {%0,%1,%2,%3}, [%4];"
                 : "=r"(r[0]), "=r"(r[1]), "=r"(r[2]), "=r"(r[3]) : "r"(addr));
}

__device__ __forceinline__ void mma16816(float c[4], const uint32_t a[4],
                                         uint32_t b0, uint32_t b1) {
    asm volatile("mma.sync.aligned.m16n8k16.row.col.f32.bf16.bf16.f32 "
                 "{%0,%1,%2,%3}, {%4,%5,%6,%7}, {%8,%9}, {%0,%1,%2,%3};"
                 : "+f"(c[0]), "+f"(c[1]), "+f"(c[2]), "+f"(c[3])
                 : "r"(a[0]), "r"(a[1]), "r"(a[2]), "r"(a[3]), "r"(b0), "r"(b1));
}

// ---------------------------------------------------------------------------
// W split precompute: Whi/Wlo bf16 for all 5 weights
// ---------------------------------------------------------------------------
__global__ void wsplit_kernel(const float* __restrict__ WA, const float* __restrict__ WB,
                              const float* __restrict__ WC, const float* __restrict__ WD,
                              const float* __restrict__ WE) {
    const float* Ws[5] = {WA, WB, WC, WD, WE};
    int w = blockIdx.y;
    int i = blockIdx.x * 256 + threadIdx.x;
    float v = Ws[w][i];
    __nv_bfloat16 hi = __float2bfloat16(v);
    g_Whi[w][i] = hi;
    g_Wlo[w][i] = __float2bfloat16(v - __bfloat162float(hi));
}

// Copy pre-split W (bf16 row-major) into swizzled smem tiles via cp.async.
__device__ __forceinline__ void copy_w(uint32_t AL, const __nv_bfloat16* Whi,
                                       const __nv_bfloat16* Wlo, int tid) {
    for (int q = tid; q < 2048; q += 256) {
        int r = q >> 4;
        int cb = (q & 15) * 16;
        cpasync16(AL + OFF_WHI + sw256(r, cb), (const char*)Whi + r * 256 + cb);
        cpasync16(AL + OFF_WLO + sw256(r, cb), (const char*)Wlo + r * 256 + cb);
    }
    CPASYNC_COMMIT();
}

// Prefetch a raw fp32 [128 x 128] tile into swizzled RAW smem via cp.async.
__device__ __forceinline__ void prefetch_raw(uint32_t AL, const float* __restrict__ srcp,
                                             long row0, long maxrow, int tid) {
    for (int q = tid; q < 4096; q += 256) {
        int r = q >> 5;
        int cb = (q & 31) * 16;
        long grow = row0 + r;
        if (grow >= maxrow) grow = maxrow - 1;   // in-bounds; zeroed at convert
        cpasync16(AL + OFF_RAW + sw512(r, cb), (const char*)srcp + grow * 512 + cb);
    }
    CPASYNC_COMMIT();
}

// Convert raw fp32 smem tile -> hi/lo bf16 swizzled tiles. thread t: row t>>1, 64 cols.
__device__ __forceinline__ void convert_raw(char* lbase, int tid, int valid_rows) {
    int r = tid >> 1;
    int c0 = (tid & 1) * 64;
    bool ok = r < valid_rows;
#pragma unroll
    for (int i = 0; i < 16; ++i) {
        int k = c0 + i * 4;
        float4 v = make_float4(0.f, 0.f, 0.f, 0.f);
        if (ok) v = *(const float4*)(lbase + OFF_RAW + sw512(r, k * 4));
        __nv_bfloat16 h0 = __float2bfloat16(v.x);
        __nv_bfloat16 h1 = __float2bfloat16(v.y);
        __nv_bfloat16 h2 = __float2bfloat16(v.z);
        __nv_bfloat16 h3 = __float2bfloat16(v.w);
        __nv_bfloat16 l0 = __float2bfloat16(v.x - __bfloat162float(h0));
        __nv_bfloat16 l1 = __float2bfloat16(v.y - __bfloat162float(h1));
        __nv_bfloat16 l2 = __float2bfloat16(v.z - __bfloat162float(h2));
        __nv_bfloat16 l3 = __float2bfloat16(v.w - __bfloat162float(h3));
        uint32_t o0 = sw256(r, k * 2);
        uint32_t o1 = sw256(r, k * 2 + 4);
        *(__nv_bfloat162*)(lbase + OFF_AHI + o0) = __nv_bfloat162(h0, h1);
        *(__nv_bfloat162*)(lbase + OFF_AHI + o1) = __nv_bfloat162(h2, h3);
        *(__nv_bfloat162*)(lbase + OFF_ALO + o0) = __nv_bfloat162(l0, l1);
        *(__nv_bfloat162*)(lbase + OFF_ALO + o1) = __nv_bfloat162(l2, l3);
    }
}

// Direct gmem->convert->smem A tile load (node kernel path)
__device__ __forceinline__ void load_tile_hilo(char* lbase, const float* __restrict__ srcp,
                                               int row0, int cnt, int tid) {
    int r = tid >> 1;
    int c0 = (tid & 1) * 64;
    int grow = row0 + r;
    const float4* rowp = (const float4*)(srcp + (size_t)grow * D);
#pragma unroll
    for (int i = 0; i < 16; ++i) {
        int k = c0 + i * 4;
        float4 v = (grow < cnt) ? rowp[k >> 2] : make_float4(0.f, 0.f, 0.f, 0.f);
        __nv_bfloat16 h0 = __float2bfloat16(v.x);
        __nv_bfloat16 h1 = __float2bfloat16(v.y);
        __nv_bfloat16 h2 = __float2bfloat16(v.z);
        __nv_bfloat16 h3 = __float2bfloat16(v.w);
        __nv_bfloat16 l0 = __float2bfloat16(v.x - __bfloat162float(h0));
        __nv_bfloat16 l1 = __float2bfloat16(v.y - __bfloat162float(h1));
        __nv_bfloat16 l2 = __float2bfloat16(v.z - __bfloat162float(h2));
        __nv_bfloat16 l3 = __float2bfloat16(v.w - __bfloat162float(h3));
        uint32_t o0 = sw256(r, k * 2);
        uint32_t o1 = sw256(r, k * 2 + 4);
        *(__nv_bfloat162*)(lbase + OFF_AHI + o0) = __nv_bfloat162(h0, h1);
        *(__nv_bfloat162*)(lbase + OFF_AHI + o1) = __nv_bfloat162(h2, h3);
        *(__nv_bfloat162*)(lbase + OFF_ALO + o0) = __nv_bfloat162(l0, l1);
        *(__nv_bfloat162*)(lbase + OFF_ALO + o1) = __nv_bfloat162(l2, l3);
    }
}

// ---------------------------------------------------------------------------
// MMA mainloop: C[128,128] = A @ W^T using 3-term bf16 split.
// Warp w: rows (w&3)*32..+31 (2 m-tiles), cols (w>>2)*64..+63 (8 n-tiles).
// ---------------------------------------------------------------------------
__device__ __forceinline__ void gemm_mma(uint32_t AL, int tid, float acc[2][8][4]) {
    int lane = tid & 31, wid = tid >> 5;
    int mtb = (wid & 3) * 32;
    int ntb = (wid >> 2) * 64;
    int lrow = lane & 15;
    int lkoff = (lane >> 4) * 16;

#pragma unroll
    for (int kc = 0; kc < 8; ++kc) {
        int kb = kc * 32;
        uint32_t ah[2][4], al[2][4];
#pragma unroll
        for (int mt = 0; mt < 2; ++mt) {
            uint32_t so = sw256(mtb + mt * 16 + lrow, kb + lkoff);
            ldm4(AL + OFF_AHI + so, ah[mt]);
            ldm4(AL + OFF_ALO + so, al[mt]);
        }
#pragma unroll
        for (int ntp = 0; ntp < 4; ++ntp) {
            uint32_t so = sw256(ntb + ntp * 16 + lrow, kb + lkoff);
            uint32_t bh[4], bl[4];
            ldm4(AL + OFF_WHI + so, bh);
            ldm4(AL + OFF_WLO + so, bl);
#pragma unroll
            for (int mt = 0; mt < 2; ++mt) {
#pragma unroll
                for (int q = 0; q < 2; ++q) {
                    float* c = acc[mt][ntp * 2 + q];
                    mma16816(c, ah[mt], bh[q], bh[q + 2]);
                    mma16816(c, ah[mt], bl[q], bl[q + 2]);
                    mma16816(c, al[mt], bh[q], bh[q + 2]);
                }
            }
        }
    }
}

// Write accumulators into the fp32 C smem tile (over A region; caller syncs first).
__device__ __forceinline__ void store_c(char* lbase, int tid, float acc[2][8][4]) {
    int lane = tid & 31, wid = tid >> 5;
    int mtb = (wid & 3) * 32;
    int ntb = (wid >> 2) * 64;
#pragma unroll
    for (int mt = 0; mt < 2; ++mt) {
#pragma unroll
        for (int nt = 0; nt < 8; ++nt) {
            int r0 = mtb + mt * 16 + (lane >> 2);
            int cb = (ntb + nt * 8 + (lane & 3) * 2) * 4;
            float* c = acc[mt][nt];
            *(float2*)(lbase + OFF_CSM + sw512(r0, cb))     = make_float2(c[0], c[1]);
            *(float2*)(lbase + OFF_CSM + sw512(r0 + 8, cb)) = make_float2(c[2], c[3]);
        }
    }
}

// ---------------------------------------------------------------------------
// Counting sort by dst
// ---------------------------------------------------------------------------
__global__ void zero_cnt_kernel(int n) {
    int i = blockIdx.x * blockDim.x + threadIdx.x;
    if (i < n) g_cnt[i] = 0;
}
__global__ void hist_kernel(const int* __restrict__ dst, int Ecnt) {
    int i = blockIdx.x * blockDim.x + threadIdx.x;
    if (i < Ecnt) atomicAdd(&g_cnt[dst[i]], 1);
}
__global__ void scan1_kernel(int n) {
    __shared__ int sm[512];
    int tid = threadIdx.x;
    int i = blockIdx.x * 512 + tid;
    int v = (i < n) ? g_cnt[i] : 0;
    sm[tid] = v;
    __syncthreads();
    for (int off = 1; off < 512; off <<= 1) {
        int t = (tid >= off) ? sm[tid - off] : 0;
        __syncthreads();
        sm[tid] += t;
        __syncthreads();
    }
    if (i < n) g_off[i] = sm[tid] - v;
    if (tid == 511) g_chunk[blockIdx.x] = sm[511];
}
__global__ void scan2_kernel(int nchunks) {
    if (threadIdx.x == 0 && blockIdx.x == 0) {
        int acc = 0;
        for (int i = 0; i < nchunks; ++i) { int t = g_chunk[i]; g_chunk[i] = acc; acc += t; }
    }
}
__global__ void scan3_kernel(int n) {
    int i = blockIdx.x * blockDim.x + threadIdx.x;
    if (i < n) { int o = g_off[i] + g_chunk[i >> 9]; g_off[i] = o; g_run[i] = o; }
}

// ---------------------------------------------------------------------------
// Node GEMMs: out = h @ W^T + b for W in {WA, WB, WD, WE} (pre-split W)
// ---------------------------------------------------------------------------
__global__ __launch_bounds__(256, 1) void node_gemm_kernel(
    const float* __restrict__ h,
    const float* __restrict__ b0, const float* __restrict__ b1,
    const float* __restrict__ b2, const float* __restrict__ b3,
    int Nn) {
    extern __shared__ char smem[];
    uint32_t sbase = smem_u32(smem);
    uint32_t AL = (sbase + 1023) & ~1023u;
    char* lbase = smem + (AL - sbase);

    int which = blockIdx.y;
    int widx          = (which == 0) ? 0 : (which == 1) ? 1 : (which == 2) ? 3 : 4;
    const float* bias = (which == 0) ? b0 : (which == 1) ? b1 : (which == 2) ? b2 : b3;
    float* out        = (which == 0) ? g_Ah : (which == 1) ? g_Bh : (which == 2) ? g_Dh : g_Eh;

    int tid = threadIdx.x;
    int row0 = blockIdx.x * 128;

    copy_w(AL, g_Whi[widx], g_Wlo[widx], tid);
    load_tile_hilo(lbase, h, row0, Nn, tid);
    CPASYNC_WAIT0();
    __syncthreads();

    float acc[2][8][4] = {};
    gemm_mma(AL, tid, acc);
    __syncthreads();
    store_c(lbase, tid, acc);
    __syncthreads();

    int r = tid >> 1;
    int ch = tid & 1;
    int row = row0 + r;
    if (row < Nn) {
        float* orow = out + (size_t)row * D;
#pragma unroll
        for (int i = 0; i < 16; ++i) {
            int col = ch * 64 + i * 4;
            float4 c4 = *(const float4*)(lbase + OFF_CSM + sw512(r, col * 4));
            float4 b4 = *(const float4*)(bias + col);
            *(float4*)(orow + col) = make_float4(c4.x + b4.x, c4.y + b4.y,
                                                 c4.z + b4.z, c4.w + b4.w);
        }
    }
}

// ---------------------------------------------------------------------------
// Fused edge kernel (pipelined, EDGE_T tiles per block, W resident):
// Ce GEMM + gather(Dh[src],Eh[dst]) + sigmoid + e_out + fp16 sigma scatter
// ---------------------------------------------------------------------------
__global__ __launch_bounds__(256, 1) void edge_kernel(
    const float* __restrict__ e,
    const int* __restrict__ src, const int* __restrict__ dst,
    const float* __restrict__ bC,
    float* __restrict__ e_out, int Ecnt, int ntiles) {
    extern __shared__ char smem[];
    uint32_t sbase = smem_u32(smem);
    uint32_t AL = (sbase + 1023) & ~1023u;
    char* lbase = smem + (AL - sbase);

    int tid = threadIdx.x;
    int t0 = blockIdx.x * EDGE_T;
    if (t0 >= ntiles) return;

    int* sSrc = (int*)(lbase + OFF_CTRL_EDGE);
    int* sDst = (int*)(lbase + OFF_CTRL_EDGE + 512);
    int* sPos = (int*)(lbase + OFF_CTRL_EDGE + 1024);

    copy_w(AL, g_Whi[2], g_Wlo[2], tid);
    prefetch_raw(AL, e, (long)t0 * 128, Ecnt, tid);
    CPASYNC_WAIT0();
    __syncthreads();

    for (int t = 0; t < EDGE_T; ++t) {
        int tile = t0 + t;
        if (tile >= ntiles) break;
        int m0 = tile * 128;
        int valid = Ecnt - m0;
        if (valid > 128) valid = 128;

        if (tid < 128) {
            int m = m0 + tid;
            sSrc[tid] = (m < Ecnt) ? src[m] : 0;
            sDst[tid] = (m < Ecnt) ? dst[m] : 0;
        }
        convert_raw(lbase, tid, valid);
        __syncthreads();   // A tiles ready; raw consumed

        if (t + 1 < EDGE_T && tile + 1 < ntiles)
            prefetch_raw(AL, e, (long)(m0 + 128), Ecnt, tid);  // overlaps MMA+epilogue

        float acc[2][8][4] = {};
        gemm_mma(AL, tid, acc);
        __syncthreads();   // all fragment reads done before C overwrites A region
        store_c(lbase, tid, acc);

        int r = tid >> 1;
        int ch = tid & 1;
        int m = m0 + r;
        if (ch == 0 && m < Ecnt) {
            int dd = sDst[r];
            int p = atomicAdd(&g_run[dd], 1);
            g_srcs[p] = sSrc[r];
            sPos[r] = p;
        }
        __syncthreads();   // C + sPos visible

        if (m < Ecnt) {
            int s = sSrc[r], dd = sDst[r];
            int pos = sPos[r];
            const float* DhS = g_Dh + (size_t)s * D;
            const float* EhD = g_Eh + (size_t)dd * D;
            const float* erow = e + (size_t)m * D;
            float* eo = e_out + (size_t)m * D;
            __half2* sigRow = (__half2*)(g_sig + (size_t)pos * D);
#pragma unroll
            for (int i = 0; i < 16; ++i) {
                int col = ch * 64 + i * 4;
                float4 c4 = *(const float4*)(lbase + OFF_CSM + sw512(r, col * 4));
                float4 b4 = *(const float4*)(bC + col);
                float4 dh = *(const float4*)(DhS + col);
                float4 eh = *(const float4*)(EhD + col);
                float4 ev = *(const float4*)(erow + col);

                float x0 = c4.x + b4.x + dh.x + eh.x;
                float x1 = c4.y + b4.y + dh.y + eh.y;
                float x2 = c4.z + b4.z + dh.z + eh.z;
                float x3 = c4.w + b4.w + dh.w + eh.w;
                float s0 = 1.f / (1.f + __expf(-x0));
                float s1 = 1.f / (1.f + __expf(-x1));
                float s2 = 1.f / (1.f + __expf(-x2));
                float s3 = 1.f / (1.f + __expf(-x3));
                *(float4*)(eo + col) = make_float4(ev.x + x0 * s0, ev.y + x1 * s1,
                                                   ev.z + x2 * s2, ev.w + x3 * s3);
                sigRow[col >> 1]       = __floats2half2_rn(s0, s1);
                sigRow[(col >> 1) + 1] = __floats2half2_rn(s2, s3);
            }
        }
        CPASYNC_WAIT0();   // next raw tile landed
        __syncthreads();   // epilogue C reads done before next convert overwrites
    }
}

// ---------------------------------------------------------------------------
// Aggregate: per-node segment sums over contiguous sorted sigma rows,
// fused with node_final (h_out = h + silu(Ah + sumMsg/(sumSig+eps)))
// ---------------------------------------------------------------------------
__global__ __launch_bounds__(256) void aggregate_kernel(
    const float* __restrict__ h, float* __restrict__ h_out, int Nn) {
    int node = blockIdx.x * 2 + (threadIdx.x >> 7);
    int j = threadIdx.x & 127;
    if (node >= Nn) return;

    int off = g_off[node];
    int cnt = g_cnt[node];
    float ssig = 0.f, smsg = 0.f;
    for (int i = 0; i < cnt; ++i) {
        float sg = __half2float(g_sig[(size_t)(off + i) * D + j]);
        int s = g_srcs[off + i];
        smsg += g_Bh[(size_t)s * D + j] * sg;
        ssig += sg;
    }
    float x = g_Ah[(size_t)node * D + j] + smsg / (ssig + 1e-6f);
    float sgm = 1.f / (1.f + __expf(-x));
    h_out[(size_t)node * D + j] = h[(size_t)node * D + j] + x * sgm;
}

extern "C" void kernel_launch(void* const* d_in, const int* in_sizes, int n_in,
                              void* d_out, int out_size) {
    const float* h   = (const float*)d_in[0];
    const float* e   = (const float*)d_in[1];
    const int*   src = (const int*)d_in[2];
    const int*   dst = (const int*)d_in[3];
    const float* WA = (const float*)d_in[4];  const float* bA = (const float*)d_in[5];
    const float* WB = (const float*)d_in[6];  const float* bB = (const float*)d_in[7];
    const float* WC = (const float*)d_in[8];  const float* bC = (const float*)d_in[9];
    const float* WD = (const float*)d_in[10]; const float* bD = (const float*)d_in[11];
    const float* WE = (const float*)d_in[12]; const float* bE = (const float*)d_in[13];

    int N = in_sizes[0] / D;
    int E = in_sizes[2];

    float* out   = (float*)d_out;
    float* h_out = out;
    float* e_out = out + (size_t)N * D;

    cudaFuncSetAttribute(node_gemm_kernel, cudaFuncAttributeMaxDynamicSharedMemorySize, SMEM_NODE);
    cudaFuncSetAttribute(edge_kernel,      cudaFuncAttributeMaxDynamicSharedMemorySize, SMEM_EDGE);

    // W hi/lo precompute
    dim3 wgrid(64, 5);
    wsplit_kernel<<<wgrid, 256>>>(WA, WB, WC, WD, WE);

    // counting sort by dst
    zero_cnt_kernel<<<(N + 255) / 256, 256>>>(N);
    hist_kernel<<<(E + 255) / 256, 256>>>(dst, E);
    int nchunks = (N + 511) / 512;
    scan1_kernel<<<nchunks, 512>>>(N);
    scan2_kernel<<<1, 32>>>(nchunks);
    scan3_kernel<<<(N + 255) / 256, 256>>>(N);

    // node GEMMs
    dim3 ngrid((N + 127) / 128, 4);
    node_gemm_kernel<<<ngrid, 256, SMEM_NODE>>>(h, bA, bB, bD, bE, N);

    // fused pipelined edge GEMM + epilogue + sigma scatter
    int ntiles = (E + 127) / 128;
    int eblocks = (ntiles + EDGE_T - 1) / EDGE_T;
    edge_kernel<<<eblocks, 256, SMEM_EDGE>>>(e, src, dst, bC, e_out, E, ntiles);

    // segment sums + node update
    aggregate_kernel<<<(N + 1) / 2, 256>>>(h, h_out, N);
}

// round 8
// speedup vs baseline: 1.0118x; 1.0118x over previous
#include <cuda_runtime.h>
#include <cuda_bf16.h>
#include <cuda_fp16.h>
#include <cstdint>

#define D 128

static constexpr int MAXN = 50000;
static constexpr int MAXE = 600000;

// Scratch (allocation-free: __device__ globals)
__device__ float g_Ah[MAXN * D];
__device__ float g_Bh[MAXN * D];
__device__ float g_Dh[MAXN * D];
__device__ float g_Eh[MAXN * D];
__device__ __half g_sig[(size_t)MAXE * D];  // sigma rows, dst-sorted, fp16
__device__ int   g_srcs[MAXE];              // src per sorted slot
__device__ int   g_cnt[MAXN];
__device__ int   g_off[MAXN];
__device__ int   g_run[MAXN];
__device__ int   g_chunk[256];
__device__ __nv_bfloat16 g_Whi[5][128 * 128];  // order: A,B,C,D,E (row-major [n][k])
__device__ __nv_bfloat16 g_Wlo[5][128 * 128];

// ---------------------------------------------------------------------------
// SMEM: [align 1024] Whi(32K) Wlo(32K) Ahi(16K) Alo(16K) ctrl(1K)  => ~98K, 2 CTA/SM
// C fp32 tile (64 x 512B = 32K) overwrites Ahi+Alo after MMA reads complete.
// ---------------------------------------------------------------------------
#define OFF_WHI 0
#define OFF_WLO 32768
#define OFF_AHI 65536
#define OFF_ALO 81920
#define OFF_CSM 65536
#define OFF_CTRL 98304
#define SMEM_DYN (1024 + 98304 + 1024)

__device__ __forceinline__ uint32_t smem_u32(const void* p) {
    uint32_t a;
    asm("{ .reg .u64 t; cvta.to.shared.u64 t, %1; cvt.u32.u64 %0, t; }" : "=r"(a) : "l"(p));
    return a;
}

// bf16 tile swizzle: row-major, 256B rows, 16B-atom XOR swizzle
__device__ __forceinline__ uint32_t sw256(int r, int cbyte) {
    uint32_t o = (uint32_t)r * 256u + (uint32_t)cbyte;
    return o ^ (((uint32_t)r & 7u) << 4);
}
// fp32 C tile swizzle: 512B rows
__device__ __forceinline__ uint32_t sw512(int r, int cbyte) {
    uint32_t o = (uint32_t)r * 512u + (uint32_t)cbyte;
    return o ^ (((uint32_t)r & 7u) << 4);
}

__device__ __forceinline__ void cpasync16(uint32_t dst, const void* src) {
    asm volatile("cp.async.cg.shared.global [%0], [%1], 16;" :: "r"(dst), "l"(src));
}
#define CPASYNC_COMMIT() asm volatile("cp.async.commit_group;" ::: "memory")
#define CPASYNC_WAIT0()  asm volatile("cp.async.wait_group 0;" ::: "memory")

__device__ __forceinline__ void ldm4(uint32_t addr, uint32_t r[4]) {
    asm volatile("ldmatrix.sync.aligned.m8n8.x4.shared.b16 {%0,%1,%2,%3}, [%4];"
                 : "=r"(r[0]), "=r"(r[1]), "=r"(r[2]), "=r"(r[3]) : "r"(addr));
}

__device__ __forceinline__ void mma16816(float c[4], const uint32_t a[4],
                                         uint32_t b0, uint32_t b1) {
    asm volatile("mma.sync.aligned.m16n8k16.row.col.f32.bf16.bf16.f32 "
                 "{%0,%1,%2,%3}, {%4,%5,%6,%7}, {%8,%9}, {%0,%1,%2,%3};"
                 : "+f"(c[0]), "+f"(c[1]), "+f"(c[2]), "+f"(c[3])
                 : "r"(a[0]), "r"(a[1]), "r"(a[2]), "r"(a[3]), "r"(b0), "r"(b1));
}

// ---------------------------------------------------------------------------
// Fused W-split (5 weights) + zero counts
// ---------------------------------------------------------------------------
__global__ void wsplit_zero_kernel(const float* __restrict__ WA, const float* __restrict__ WB,
                                   const float* __restrict__ WC, const float* __restrict__ WD,
                                   const float* __restrict__ WE, int Nn) {
    if (blockIdx.y < 5) {
        const float* Ws[5] = {WA, WB, WC, WD, WE};
        int w = blockIdx.y;
        int i = blockIdx.x * 256 + threadIdx.x;
        float v = Ws[w][i];
        __nv_bfloat16 hi = __float2bfloat16(v);
        g_Whi[w][i] = hi;
        g_Wlo[w][i] = __float2bfloat16(v - __bfloat162float(hi));
    } else {
        for (int i = blockIdx.x * 256 + threadIdx.x; i < Nn; i += 64 * 256)
            g_cnt[i] = 0;
    }
}

// Copy pre-split W (bf16 row-major [128][128]) into swizzled smem via cp.async.
__device__ __forceinline__ void copy_w(uint32_t AL, const __nv_bfloat16* Whi,
                                       const __nv_bfloat16* Wlo, int tid) {
    for (int q = tid; q < 2048; q += 256) {
        int r = q >> 4;
        int cb = (q & 15) * 16;
        cpasync16(AL + OFF_WHI + sw256(r, cb), (const char*)Whi + r * 256 + cb);
        cpasync16(AL + OFF_WLO + sw256(r, cb), (const char*)Wlo + r * 256 + cb);
    }
    CPASYNC_COMMIT();
}

// Load a [64 x 128] fp32 tile -> hi/lo bf16 swizzled smem. thread t: row t>>2, 32 cols.
__device__ __forceinline__ void load_tile_hilo(char* lbase, const float* __restrict__ srcp,
                                               int row0, int cnt, int tid) {
    int r = tid >> 2;
    int c0 = (tid & 3) * 32;
    int grow = row0 + r;
    const float4* rowp = (const float4*)(srcp + (size_t)grow * D);
#pragma unroll
    for (int i = 0; i < 8; ++i) {
        int k = c0 + i * 4;
        float4 v = (grow < cnt) ? rowp[k >> 2] : make_float4(0.f, 0.f, 0.f, 0.f);
        __nv_bfloat16 h0 = __float2bfloat16(v.x);
        __nv_bfloat16 h1 = __float2bfloat16(v.y);
        __nv_bfloat16 h2 = __float2bfloat16(v.z);
        __nv_bfloat16 h3 = __float2bfloat16(v.w);
        __nv_bfloat16 l0 = __float2bfloat16(v.x - __bfloat162float(h0));
        __nv_bfloat16 l1 = __float2bfloat16(v.y - __bfloat162float(h1));
        __nv_bfloat16 l2 = __float2bfloat16(v.z - __bfloat162float(h2));
        __nv_bfloat16 l3 = __float2bfloat16(v.w - __bfloat162float(h3));
        uint32_t o0 = sw256(r, k * 2);
        uint32_t o1 = sw256(r, k * 2 + 4);
        *(__nv_bfloat162*)(lbase + OFF_AHI + o0) = __nv_bfloat162(h0, h1);
        *(__nv_bfloat162*)(lbase + OFF_AHI + o1) = __nv_bfloat162(h2, h3);
        *(__nv_bfloat162*)(lbase + OFF_ALO + o0) = __nv_bfloat162(l0, l1);
        *(__nv_bfloat162*)(lbase + OFF_ALO + o1) = __nv_bfloat162(l2, l3);
    }
}

// ---------------------------------------------------------------------------
// MMA mainloop: C[64,128] = A @ W^T, 3-term bf16 split.
// Warp w: m-tile (w&3)*16 (16 rows), n-half (w>>2)*64 (64 cols).
// ---------------------------------------------------------------------------
__device__ __forceinline__ void gemm_mma(uint32_t AL, int tid, float acc[8][4]) {
    int lane = tid & 31, wid = tid >> 5;
    int mtb = (wid & 3) * 16;
    int ntb = (wid >> 2) * 64;
    int lrow = lane & 15;
    int lkoff = (lane >> 4) * 16;

#pragma unroll
    for (int kc = 0; kc < 8; ++kc) {
        int kb = kc * 32;
        uint32_t ah[4], al[4];
        uint32_t soa = sw256(mtb + lrow, kb + lkoff);
        ldm4(AL + OFF_AHI + soa, ah);
        ldm4(AL + OFF_ALO + soa, al);
#pragma unroll
        for (int ntp = 0; ntp < 4; ++ntp) {
            uint32_t so = sw256(ntb + ntp * 16 + lrow, kb + lkoff);
            uint32_t bh[4], bl[4];
            ldm4(AL + OFF_WHI + so, bh);
            ldm4(AL + OFF_WLO + so, bl);
#pragma unroll
            for (int q = 0; q < 2; ++q) {
                float* c = acc[ntp * 2 + q];
                mma16816(c, ah, bh[q], bh[q + 2]);
                mma16816(c, ah, bl[q], bl[q + 2]);
                mma16816(c, al, bh[q], bh[q + 2]);
            }
        }
    }
}

// Write accumulators into the fp32 C smem tile (over A region; caller syncs first).
__device__ __forceinline__ void store_c(char* lbase, int tid, float acc[8][4]) {
    int lane = tid & 31, wid = tid >> 5;
    int mtb = (wid & 3) * 16;
    int ntb = (wid >> 2) * 64;
#pragma unroll
    for (int nt = 0; nt < 8; ++nt) {
        int r0 = mtb + (lane >> 2);
        int cb = (ntb + nt * 8 + (lane & 3) * 2) * 4;
        float* c = acc[nt];
        *(float2*)(lbase + OFF_CSM + sw512(r0, cb))     = make_float2(c[0], c[1]);
        *(float2*)(lbase + OFF_CSM + sw512(r0 + 8, cb)) = make_float2(c[2], c[3]);
    }
}

// ---------------------------------------------------------------------------
// Counting sort by dst (scan2 folded into scan3)
// ---------------------------------------------------------------------------
__global__ void hist_kernel(const int* __restrict__ dst, int Ecnt) {
    int i = blockIdx.x * blockDim.x + threadIdx.x;
    if (i < Ecnt) atomicAdd(&g_cnt[dst[i]], 1);
}
__global__ void scan1_kernel(int n) {
    __shared__ int sm[512];
    int tid = threadIdx.x;
    int i = blockIdx.x * 512 + tid;
    int v = (i < n) ? g_cnt[i] : 0;
    sm[tid] = v;
    __syncthreads();
    for (int off = 1; off < 512; off <<= 1) {
        int t = (tid >= off) ? sm[tid - off] : 0;
        __syncthreads();
        sm[tid] += t;
        __syncthreads();
    }
    if (i < n) g_off[i] = sm[tid] - v;
    if (tid == 511) g_chunk[blockIdx.x] = sm[511];
}
__global__ void scan3_kernel(int n) {
    __shared__ int pre;
    if (threadIdx.x == 0) {
        int acc = 0;
        for (int j = 0; j < blockIdx.x; ++j) acc += g_chunk[j];
        pre = acc;
    }
    __syncthreads();
    int i = blockIdx.x * 512 + threadIdx.x;
    if (i < n) {
        int o = g_off[i] + pre;
        g_off[i] = o;
        g_run[i] = o;
    }
}

// ---------------------------------------------------------------------------
// Node GEMMs: out = h @ W^T + b for W in {WA, WB, WD, WE} (pre-split W)
// ---------------------------------------------------------------------------
__global__ __launch_bounds__(256, 2) void node_gemm_kernel(
    const float* __restrict__ h,
    const float* __restrict__ b0, const float* __restrict__ b1,
    const float* __restrict__ b2, const float* __restrict__ b3,
    int Nn) {
    extern __shared__ char smem[];
    uint32_t sbase = smem_u32(smem);
    uint32_t AL = (sbase + 1023) & ~1023u;
    char* lbase = smem + (AL - sbase);

    int which = blockIdx.y;
    int widx          = (which == 0) ? 0 : (which == 1) ? 1 : (which == 2) ? 3 : 4;
    const float* bias = (which == 0) ? b0 : (which == 1) ? b1 : (which == 2) ? b2 : b3;
    float* out        = (which == 0) ? g_Ah : (which == 1) ? g_Bh : (which == 2) ? g_Dh : g_Eh;

    int tid = threadIdx.x;
    int row0 = blockIdx.x * 64;

    copy_w(AL, g_Whi[widx], g_Wlo[widx], tid);
    load_tile_hilo(lbase, h, row0, Nn, tid);
    CPASYNC_WAIT0();
    __syncthreads();

    float acc[8][4] = {};
    gemm_mma(AL, tid, acc);
    __syncthreads();
    store_c(lbase, tid, acc);
    __syncthreads();

    int r = tid >> 2;
    int ch = tid & 3;
    int row = row0 + r;
    if (row < Nn) {
        float* orow = out + (size_t)row * D;
#pragma unroll
        for (int i = 0; i < 8; ++i) {
            int col = ch * 32 + i * 4;
            float4 c4 = *(const float4*)(lbase + OFF_CSM + sw512(r, col * 4));
            float4 b4 = *(const float4*)(bias + col);
            *(float4*)(orow + col) = make_float4(c4.x + b4.x, c4.y + b4.y,
                                                 c4.z + b4.z, c4.w + b4.w);
        }
    }
}

// ---------------------------------------------------------------------------
// Fused edge kernel (64 edges per block, 2 CTA/SM):
// Ce GEMM + gather(Dh[src],Eh[dst]) + sigmoid + e_out + fp16 sigma scatter
// ---------------------------------------------------------------------------
__global__ __launch_bounds__(256, 2) void edge_kernel(
    const float* __restrict__ e,
    const int* __restrict__ src, const int* __restrict__ dst,
    const float* __restrict__ bC,
    float* __restrict__ e_out, int Ecnt) {
    extern __shared__ char smem[];
    uint32_t sbase = smem_u32(smem);
    uint32_t AL = (sbase + 1023) & ~1023u;
    char* lbase = smem + (AL - sbase);

    int tid = threadIdx.x;
    int m0 = blockIdx.x * 64;

    int* sSrc = (int*)(lbase + OFF_CTRL);
    int* sDst = (int*)(lbase + OFF_CTRL + 256);
    int* sPos = (int*)(lbase + OFF_CTRL + 512);

    copy_w(AL, g_Whi[2], g_Wlo[2], tid);
    load_tile_hilo(lbase, e, m0, Ecnt, tid);
    if (tid < 64) {
        int m = m0 + tid;
        sSrc[tid] = (m < Ecnt) ? src[m] : 0;
        sDst[tid] = (m < Ecnt) ? dst[m] : 0;
    }
    CPASYNC_WAIT0();
    __syncthreads();

    float acc[8][4] = {};
    gemm_mma(AL, tid, acc);
    __syncthreads();   // fragment reads done before C overwrites A region
    store_c(lbase, tid, acc);

    int r = tid >> 2;
    int ch = tid & 3;
    int m = m0 + r;
    if (ch == 0 && m < Ecnt) {
        int dd = sDst[r];
        int p = atomicAdd(&g_run[dd], 1);
        g_srcs[p] = sSrc[r];
        sPos[r] = p;
    }
    __syncthreads();   // C + sPos visible

    if (m < Ecnt) {
        int s = sSrc[r], dd = sDst[r];
        int pos = sPos[r];
        const float* DhS = g_Dh + (size_t)s * D;
        const float* EhD = g_Eh + (size_t)dd * D;
        const float* erow = e + (size_t)m * D;
        float* eo = e_out + (size_t)m * D;
        __half2* sigRow = (__half2*)(g_sig + (size_t)pos * D);
#pragma unroll
        for (int i = 0; i < 8; ++i) {
            int col = ch * 32 + i * 4;
            float4 c4 = *(const float4*)(lbase + OFF_CSM + sw512(r, col * 4));
            float4 b4 = *(const float4*)(bC + col);
            float4 dh = *(const float4*)(DhS + col);
            float4 eh = *(const float4*)(EhD + col);
            float4 ev = *(const float4*)(erow + col);

            float x0 = c4.x + b4.x + dh.x + eh.x;
            float x1 = c4.y + b4.y + dh.y + eh.y;
            float x2 = c4.z + b4.z + dh.z + eh.z;
            float x3 = c4.w + b4.w + dh.w + eh.w;
            float s0 = 1.f / (1.f + __expf(-x0));
            float s1 = 1.f / (1.f + __expf(-x1));
            float s2 = 1.f / (1.f + __expf(-x2));
            float s3 = 1.f / (1.f + __expf(-x3));
            *(float4*)(eo + col) = make_float4(ev.x + x0 * s0, ev.y + x1 * s1,
                                               ev.z + x2 * s2, ev.w + x3 * s3);
            sigRow[col >> 1]       = __floats2half2_rn(s0, s1);
            sigRow[(col >> 1) + 1] = __floats2half2_rn(s2, s3);
        }
    }
}

// ---------------------------------------------------------------------------
// Aggregate: per-node segment sums over contiguous sorted sigma rows,
// fused with node_final (h_out = h + silu(Ah + sumMsg/(sumSig+eps)))
// ---------------------------------------------------------------------------
__global__ __launch_bounds__(256) void aggregate_kernel(
    const float* __restrict__ h, float* __restrict__ h_out, int Nn) {
    int node = blockIdx.x * 2 + (threadIdx.x >> 7);
    int j = threadIdx.x & 127;
    if (node >= Nn) return;

    int off = g_off[node];
    int cnt = g_cnt[node];
    float ssig = 0.f, smsg = 0.f;
    for (int i = 0; i < cnt; ++i) {
        float sg = __half2float(g_sig[(size_t)(off + i) * D + j]);
        int s = g_srcs[off + i];
        smsg += g_Bh[(size_t)s * D + j] * sg;
        ssig += sg;
    }
    float x = g_Ah[(size_t)node * D + j] + smsg / (ssig + 1e-6f);
    float sgm = 1.f / (1.f + __expf(-x));
    h_out[(size_t)node * D + j] = h[(size_t)node * D + j] + x * sgm;
}

extern "C" void kernel_launch(void* const* d_in, const int* in_sizes, int n_in,
                              void* d_out, int out_size) {
    const float* h   = (const float*)d_in[0];
    const float* e   = (const float*)d_in[1];
    const int*   src = (const int*)d_in[2];
    const int*   dst = (const int*)d_in[3];
    const float* WA = (const float*)d_in[4];  const float* bA = (const float*)d_in[5];
    const float* WB = (const float*)d_in[6];  const float* bB = (const float*)d_in[7];
    const float* WC = (const float*)d_in[8];  const float* bC = (const float*)d_in[9];
    const float* WD = (const float*)d_in[10]; const float* bD = (const float*)d_in[11];
    const float* WE = (const float*)d_in[12]; const float* bE = (const float*)d_in[13];

    int N = in_sizes[0] / D;
    int E = in_sizes[2];

    float* out   = (float*)d_out;
    float* h_out = out;
    float* e_out = out + (size_t)N * D;

    cudaFuncSetAttribute(node_gemm_kernel, cudaFuncAttributeMaxDynamicSharedMemorySize, SMEM_DYN);
    cudaFuncSetAttribute(edge_kernel,      cudaFuncAttributeMaxDynamicSharedMemorySize, SMEM_DYN);

    // 1: W hi/lo split + zero counts
    dim3 wgrid(64, 6);
    wsplit_zero_kernel<<<wgrid, 256>>>(WA, WB, WC, WD, WE, N);
    // 2: histogram
    hist_kernel<<<(E + 255) / 256, 256>>>(dst, E);
    // 3: per-chunk scan
    int nchunks = (N + 511) / 512;
    scan1_kernel<<<nchunks, 512>>>(N);
    // 4: node GEMMs (profiled launch)
    dim3 ngrid((N + 63) / 64, 4);
    node_gemm_kernel<<<ngrid, 256, SMEM_DYN>>>(h, bA, bB, bD, bE, N);
    // 5: finish scan (prefix of chunks folded in)
    scan3_kernel<<<nchunks, 512>>>(N);
    // 6: fused edge GEMM + epilogue + sigma scatter
    edge_kernel<<<(E + 63) / 64, 256, SMEM_DYN>>>(e, src, dst, bC, e_out, E);
    // 7: segment sums + node update
    aggregate_kernel<<<(N + 1) / 2, 256>>>(h, h_out, N);
}

// round 10
// speedup vs baseline: 1.0953x; 1.0826x over previous
#include <cuda_runtime.h>
#include <cuda_bf16.h>
#include <cuda_fp16.h>
#include <cstdint>

#define D 128

static constexpr int MAXN = 50000;
static constexpr int MAXE = 600000;

// Scratch (allocation-free: __device__ globals)
__device__ float g_Ah[MAXN * D];
__device__ float g_Bh[MAXN * D];
__device__ float g_Dh[MAXN * D];
__device__ float g_Eh[MAXN * D];
__device__ __half g_sig[(size_t)MAXE * D];  // sigma rows, dst-sorted, fp16
__device__ int   g_srcs[MAXE];              // src per sorted slot
__device__ int   g_cnt[MAXN];
__device__ int   g_off[MAXN];
__device__ int   g_run[MAXN];
__device__ int   g_chunk[256];
__device__ __nv_bfloat16 g_Whi[5][128 * 128];  // order: A,B,C,D,E (row-major [n][k])
__device__ __nv_bfloat16 g_Wlo[5][128 * 128];

// ---------------------------------------------------------------------------
// SMEM: [align 1024] Whi(32K) Wlo(32K) Ahi(16K) Alo(16K) ctrl(1K)  => ~98K, 2 CTA/SM
// C fp32 tile (64 x 512B = 32K) overwrites Ahi+Alo after MMA reads complete.
// ---------------------------------------------------------------------------
#define OFF_WHI 0
#define OFF_WLO 32768
#define OFF_AHI 65536
#define OFF_ALO 81920
#define OFF_CSM 65536
#define OFF_CTRL 98304
#define SMEM_DYN (1024 + 98304 + 1024)

__device__ __forceinline__ uint32_t smem_u32(const void* p) {
    uint32_t a;
    asm("{ .reg .u64 t; cvta.to.shared.u64 t, %1; cvt.u32.u64 %0, t; }" : "=r"(a) : "l"(p));
    return a;
}

// bf16 tile swizzle: row-major, 256B rows, 16B-atom XOR swizzle
__device__ __forceinline__ uint32_t sw256(int r, int cbyte) {
    uint32_t o = (uint32_t)r * 256u + (uint32_t)cbyte;
    return o ^ (((uint32_t)r & 7u) << 4);
}
// fp32 C tile swizzle: 512B rows
__device__ __forceinline__ uint32_t sw512(int r, int cbyte) {
    uint32_t o = (uint32_t)r * 512u + (uint32_t)cbyte;
    return o ^ (((uint32_t)r & 7u) << 4);
}

__device__ __forceinline__ void cpasync16(uint32_t dst, const void* src) {
    asm volatile("cp.async.cg.shared.global [%0], [%1], 16;" :: "r"(dst), "l"(src));
}
#define CPASYNC_COMMIT() asm volatile("cp.async.commit_group;" ::: "memory")
#define CPASYNC_WAIT0()  asm volatile("cp.async.wait_group 0;" ::: "memory")

__device__ __forceinline__ void ldm4(uint32_t addr, uint32_t r[4]) {
    asm volatile("ldmatrix.sync.aligned.m8n8.x4.shared.b16 {%0,%1,%2,%3}, [%4];"
                 : "=r"(r[0]), "=r"(r[1]), "=r"(r[2]), "=r"(r[3]) : "r"(addr));
}

__device__ __forceinline__ void mma16816(float c[4], const uint32_t a[4],
                                         uint32_t b0, uint32_t b1) {
    asm volatile("mma.sync.aligned.m16n8k16.row.col.f32.bf16.bf16.f32 "
                 "{%0,%1,%2,%3}, {%4,%5,%6,%7}, {%8,%9}, {%0,%1,%2,%3};"
                 : "+f"(c[0]), "+f"(c[1]), "+f"(c[2]), "+f"(c[3])
                 : "r"(a[0]), "r"(a[1]), "r"(a[2]), "r"(a[3]), "r"(b0), "r"(b1));
}

__device__ __forceinline__ uint32_t pack_bf2(float x, float y) {
    __nv_bfloat162 t = __floats2bfloat162_rn(x, y);
    return *reinterpret_cast<uint32_t*>(&t);
}

// ---------------------------------------------------------------------------
// Fused W-split (5 weights) + zero counts
// ---------------------------------------------------------------------------
__global__ void wsplit_zero_kernel(const float* __restrict__ WA, const float* __restrict__ WB,
                                   const float* __restrict__ WC, const float* __restrict__ WD,
                                   const float* __restrict__ WE, int Nn) {
    if (blockIdx.y < 5) {
        const float* Ws[5] = {WA, WB, WC, WD, WE};
        int w = blockIdx.y;
        int i = blockIdx.x * 256 + threadIdx.x;
        float v = Ws[w][i];
        __nv_bfloat16 hi = __float2bfloat16(v);
        g_Whi[w][i] = hi;
        g_Wlo[w][i] = __float2bfloat16(v - __bfloat162float(hi));
    } else {
        for (int i = blockIdx.x * 256 + threadIdx.x; i < Nn; i += 64 * 256)
            g_cnt[i] = 0;
    }
}

// Copy pre-split W (bf16 row-major [128][128]) into swizzled smem via cp.async.
__device__ __forceinline__ void copy_w(uint32_t AL, const __nv_bfloat16* Whi,
                                       const __nv_bfloat16* Wlo, int tid) {
    for (int q = tid; q < 2048; q += 256) {
        int r = q >> 4;
        int cb = (q & 15) * 16;
        cpasync16(AL + OFF_WHI + sw256(r, cb), (const char*)Whi + r * 256 + cb);
        cpasync16(AL + OFF_WLO + sw256(r, cb), (const char*)Wlo + r * 256 + cb);
    }
    CPASYNC_COMMIT();
}

// Load a [64 x 128] fp32 tile -> hi/lo bf16 swizzled smem (8B STS).
// thread t: row t>>2, cols (t&3)*32 .. +31.
__device__ __forceinline__ void load_tile_hilo(char* lbase, const float* __restrict__ srcp,
                                               int row0, int cnt, int tid) {
    int r = tid >> 2;
    int c0 = (tid & 3) * 32;
    int grow = row0 + r;
    const float4* rowp = (const float4*)(srcp + (size_t)grow * D);
#pragma unroll
    for (int i = 0; i < 8; ++i) {
        int k = c0 + i * 4;
        float4 v = (grow < cnt) ? rowp[k >> 2] : make_float4(0.f, 0.f, 0.f, 0.f);
        __nv_bfloat16 h0 = __float2bfloat16(v.x);
        __nv_bfloat16 h1 = __float2bfloat16(v.y);
        __nv_bfloat16 h2 = __float2bfloat16(v.z);
        __nv_bfloat16 h3 = __float2bfloat16(v.w);
        uint32_t hi01 = pack_bf2(v.x, v.y);     // rn == float2bfloat16 per element
        uint32_t hi23 = pack_bf2(v.z, v.w);
        uint32_t lo01 = pack_bf2(v.x - __bfloat162float(h0), v.y - __bfloat162float(h1));
        uint32_t lo23 = pack_bf2(v.z - __bfloat162float(h2), v.w - __bfloat162float(h3));
        uint32_t o = sw256(r, k * 2);   // k%4==0 -> 8B aligned within 16B atom
        *(uint2*)(lbase + OFF_AHI + o) = make_uint2(hi01, hi23);
        *(uint2*)(lbase + OFF_ALO + o) = make_uint2(lo01, lo23);
    }
}

// ---------------------------------------------------------------------------
// MMA mainloop: C[64,128] = A @ W^T, 3-term bf16 split.
// Warp w: rows (w&1)*32 (2 m-tiles), cols (w>>1)*32 (2 B-tiles = 4 n8).
// ---------------------------------------------------------------------------
__device__ __forceinline__ void gemm_mma(uint32_t AL, int tid, float acc[2][2][2][4]) {
    int lane = tid & 31, wid = tid >> 5;
    int mtb = (wid & 1) * 32;
    int ntb = (wid >> 1) * 32;
    int lrow = lane & 15;
    int lkoff = (lane >> 4) * 16;

#pragma unroll
    for (int kc = 0; kc < 8; ++kc) {
        int kb = kc * 32;
        uint32_t ah[2][4], al[2][4], bh[2][4], bl[2][4];
#pragma unroll
        for (int mt = 0; mt < 2; ++mt) {
            uint32_t so = sw256(mtb + mt * 16 + lrow, kb + lkoff);
            ldm4(AL + OFF_AHI + so, ah[mt]);
            ldm4(AL + OFF_ALO + so, al[mt]);
        }
#pragma unroll
        for (int nt = 0; nt < 2; ++nt) {
            uint32_t so = sw256(ntb + nt * 16 + lrow, kb + lkoff);
            ldm4(AL + OFF_WHI + so, bh[nt]);
            ldm4(AL + OFF_WLO + so, bl[nt]);
        }
#pragma unroll
        for (int mt = 0; mt < 2; ++mt)
#pragma unroll
            for (int nt = 0; nt < 2; ++nt)
#pragma unroll
                for (int q = 0; q < 2; ++q) {
                    float* c = acc[mt][nt][q];
                    mma16816(c, ah[mt], bh[nt][q], bh[nt][q + 2]);
                    mma16816(c, ah[mt], bl[nt][q], bl[nt][q + 2]);
                    mma16816(c, al[mt], bh[nt][q], bh[nt][q + 2]);
                }
    }
}

// Write accumulators into the fp32 C smem tile (over A region; caller syncs first).
__device__ __forceinline__ void store_c(char* lbase, int tid, float acc[2][2][2][4]) {
    int lane = tid & 31, wid = tid >> 5;
    int mtb = (wid & 1) * 32;
    int ntb = (wid >> 1) * 32;
#pragma unroll
    for (int mt = 0; mt < 2; ++mt)
#pragma unroll
        for (int nt = 0; nt < 2; ++nt)
#pragma unroll
            for (int q = 0; q < 2; ++q) {
                int r0 = mtb + mt * 16 + (lane >> 2);
                int cb = (ntb + nt * 16 + q * 8 + (lane & 3) * 2) * 4;
                float* c = acc[mt][nt][q];
                *(float2*)(lbase + OFF_CSM + sw512(r0, cb))     = make_float2(c[0], c[1]);
                *(float2*)(lbase + OFF_CSM + sw512(r0 + 8, cb)) = make_float2(c[2], c[3]);
            }
}

// ---------------------------------------------------------------------------
// Counting sort by dst (scan2 folded into scan3)
// ---------------------------------------------------------------------------
__global__ void hist_kernel(const int* __restrict__ dst, int Ecnt) {
    int i = blockIdx.x * blockDim.x + threadIdx.x;
    if (i < Ecnt) atomicAdd(&g_cnt[dst[i]], 1);
}
__global__ void scan1_kernel(int n) {
    __shared__ int sm[512];
    int tid = threadIdx.x;
    int i = blockIdx.x * 512 + tid;
    int v = (i < n) ? g_cnt[i] : 0;
    sm[tid] = v;
    __syncthreads();
    for (int off = 1; off < 512; off <<= 1) {
        int t = (tid >= off) ? sm[tid - off] : 0;
        __syncthreads();
        sm[tid] += t;
        __syncthreads();
    }
    if (i < n) g_off[i] = sm[tid] - v;
    if (tid == 511) g_chunk[blockIdx.x] = sm[511];
}
__global__ void scan3_kernel(int n) {
    __shared__ int pre;
    if (threadIdx.x == 0) {
        int acc = 0;
        for (int j = 0; j < blockIdx.x; ++j) acc += g_chunk[j];
        pre = acc;
    }
    __syncthreads();
    int i = blockIdx.x * 512 + threadIdx.x;
    if (i < n) {
        int o = g_off[i] + pre;
        g_off[i] = o;
        g_run[i] = o;
    }
}

// ---------------------------------------------------------------------------
// Node GEMMs: out = h @ W^T + b; direct fragment->gmem epilogue (no C smem)
// ---------------------------------------------------------------------------
__global__ __launch_bounds__(256, 2) void node_gemm_kernel(
    const float* __restrict__ h,
    const float* __restrict__ b0, const float* __restrict__ b1,
    const float* __restrict__ b2, const float* __restrict__ b3,
    int Nn) {
    extern __shared__ char smem[];
    uint32_t sbase = smem_u32(smem);
    uint32_t AL = (sbase + 1023) & ~1023u;
    char* lbase = smem + (AL - sbase);

    int which = blockIdx.y;
    int widx          = (which == 0) ? 0 : (which == 1) ? 1 : (which == 2) ? 3 : 4;
    const float* bias = (which == 0) ? b0 : (which == 1) ? b1 : (which == 2) ? b2 : b3;
    float* out        = (which == 0) ? g_Ah : (which == 1) ? g_Bh : (which == 2) ? g_Dh : g_Eh;

    int tid = threadIdx.x;
    int row0 = blockIdx.x * 64;

    copy_w(AL, g_Whi[widx], g_Wlo[widx], tid);
    load_tile_hilo(lbase, h, row0, Nn, tid);
    CPASYNC_WAIT0();
    __syncthreads();

    float acc[2][2][2][4] = {};
    gemm_mma(AL, tid, acc);

    // direct epilogue from fragments
    int lane = tid & 31, wid = tid >> 5;
    int mtb = (wid & 1) * 32;
    int ntb = (wid >> 1) * 32;
#pragma unroll
    for (int mt = 0; mt < 2; ++mt)
#pragma unroll
        for (int nt = 0; nt < 2; ++nt)
#pragma unroll
            for (int q = 0; q < 2; ++q) {
                int r0 = row0 + mtb + mt * 16 + (lane >> 2);
                int col = ntb + nt * 16 + q * 8 + (lane & 3) * 2;
                float2 b2v = *(const float2*)(bias + col);
                float* c = acc[mt][nt][q];
                if (r0 < Nn)
                    *(float2*)(out + (size_t)r0 * D + col) =
                        make_float2(c[0] + b2v.x, c[1] + b2v.y);
                if (r0 + 8 < Nn)
                    *(float2*)(out + (size_t)(r0 + 8) * D + col) =
                        make_float2(c[2] + b2v.x, c[3] + b2v.y);
            }
}

// ---------------------------------------------------------------------------
// Fused edge kernel (64 edges per block, 2 CTA/SM):
// Ce GEMM + gather(Dh[src],Eh[dst]) + sigmoid + e_out + fp16 sigma scatter
// ---------------------------------------------------------------------------
__global__ __launch_bounds__(256, 2) void edge_kernel(
    const float* __restrict__ e,
    const int* __restrict__ src, const int* __restrict__ dst,
    const float* __restrict__ bC,
    float* __restrict__ e_out, int Ecnt) {
    extern __shared__ char smem[];
    uint32_t sbase = smem_u32(smem);
    uint32_t AL = (sbase + 1023) & ~1023u;
    char* lbase = smem + (AL - sbase);

    int tid = threadIdx.x;
    int m0 = blockIdx.x * 64;

    int* sSrc = (int*)(lbase + OFF_CTRL);
    int* sDst = (int*)(lbase + OFF_CTRL + 256);
    int* sPos = (int*)(lbase + OFF_CTRL + 512);

    copy_w(AL, g_Whi[2], g_Wlo[2], tid);
    load_tile_hilo(lbase, e, m0, Ecnt, tid);
    if (tid < 64) {
        int m = m0 + tid;
        sSrc[tid] = (m < Ecnt) ? src[m] : 0;
        sDst[tid] = (m < Ecnt) ? dst[m] : 0;
    }
    CPASYNC_WAIT0();
    __syncthreads();

    float acc[2][2][2][4] = {};
    gemm_mma(AL, tid, acc);
    __syncthreads();   // fragment reads done before C overwrites A region
    store_c(lbase, tid, acc);

    int r = tid >> 2;
    int ch = tid & 3;
    int m = m0 + r;
    if (ch == 0 && m < Ecnt) {
        int dd = sDst[r];
        int p = atomicAdd(&g_run[dd], 1);
        g_srcs[p] = sSrc[r];
        sPos[r] = p;
    }
    __syncthreads();   // C + sPos visible

    if (m < Ecnt) {
        int s = sSrc[r], dd = sDst[r];
        int pos = sPos[r];
        const float* DhS = g_Dh + (size_t)s * D;
        const float* EhD = g_Eh + (size_t)dd * D;
        const float* erow = e + (size_t)m * D;
        float* eo = e_out + (size_t)m * D;
        __half2* sigRow = (__half2*)(g_sig + (size_t)pos * D);
#pragma unroll
        for (int i = 0; i < 8; ++i) {
            int col = ch * 32 + i * 4;
            float4 c4 = *(const float4*)(lbase + OFF_CSM + sw512(r, col * 4));
            float4 b4 = *(const float4*)(bC + col);
            float4 dh = *(const float4*)(DhS + col);
            float4 eh = *(const float4*)(EhD + col);
            float4 ev = *(const float4*)(erow + col);

            float x0 = c4.x + b4.x + dh.x + eh.x;
            float x1 = c4.y + b4.y + dh.y + eh.y;
            float x2 = c4.z + b4.z + dh.z + eh.z;
            float x3 = c4.w + b4.w + dh.w + eh.w;
            float s0 = 1.f / (1.f + __expf(-x0));
            float s1 = 1.f / (1.f + __expf(-x1));
            float s2 = 1.f / (1.f + __expf(-x2));
            float s3 = 1.f / (1.f + __expf(-x3));
            *(float4*)(eo + col) = make_float4(ev.x + x0 * s0, ev.y + x1 * s1,
                                               ev.z + x2 * s2, ev.w + x3 * s3);
            sigRow[col >> 1]       = __floats2half2_rn(s0, s1);
            sigRow[(col >> 1) + 1] = __floats2half2_rn(s2, s3);
        }
    }
}

// ---------------------------------------------------------------------------
// Aggregate (vectorized half2/float2): per-node segment sums + node_final
// ---------------------------------------------------------------------------
__global__ __launch_bounds__(256) void aggregate_kernel(
    const float* __restrict__ h, float* __restrict__ h_out, int Nn) {
    int node = blockIdx.x * 4 + (threadIdx.x >> 6);
    int j2 = threadIdx.x & 63;   // column-pair index
    if (node >= Nn) return;

    int off = g_off[node];
    int cnt = g_cnt[node];
    const __half2* sig2 = (const __half2*)g_sig;
    float ss0 = 0.f, ss1 = 0.f, sm0 = 0.f, sm1 = 0.f;
    for (int i = 0; i < cnt; ++i) {
        float2 sg = __half22float2(sig2[(size_t)(off + i) * 64 + j2]);
        int s = g_srcs[off + i];
        float2 bh = *(const float2*)(g_Bh + (size_t)s * D + j2 * 2);
        sm0 += bh.x * sg.x; sm1 += bh.y * sg.y;
        ss0 += sg.x; ss1 += sg.y;
    }
    float2 ah = *(const float2*)(g_Ah + (size_t)node * D + j2 * 2);
    float x0 = ah.x + sm0 / (ss0 + 1e-6f);
    float x1 = ah.y + sm1 / (ss1 + 1e-6f);
    float g0 = 1.f / (1.f + __expf(-x0));
    float g1 = 1.f / (1.f + __expf(-x1));
    float2 hv = *(const float2*)(h + (size_t)node * D + j2 * 2);
    *(float2*)(h_out + (size_t)node * D + j2 * 2) =
        make_float2(hv.x + x0 * g0, hv.y + x1 * g1);
}

extern "C" void kernel_launch(void* const* d_in, const int* in_sizes, int n_in,
                              void* d_out, int out_size) {
    const float* h   = (const float*)d_in[0];
    const float* e   = (const float*)d_in[1];
    const int*   src = (const int*)d_in[2];
    const int*   dst = (const int*)d_in[3];
    const float* WA = (const float*)d_in[4];  const float* bA = (const float*)d_in[5];
    const float* WB = (const float*)d_in[6];  const float* bB = (const float*)d_in[7];
    const float* WC = (const float*)d_in[8];  const float* bC = (const float*)d_in[9];
    const float* WD = (const float*)d_in[10]; const float* bD = (const float*)d_in[11];
    const float* WE = (const float*)d_in[12]; const float* bE = (const float*)d_in[13];

    int N = in_sizes[0] / D;
    int E = in_sizes[2];

    float* out   = (float*)d_out;
    float* h_out = out;
    float* e_out = out + (size_t)N * D;

    cudaFuncSetAttribute(node_gemm_kernel, cudaFuncAttributeMaxDynamicSharedMemorySize, SMEM_DYN);
    cudaFuncSetAttribute(edge_kernel,      cudaFuncAttributeMaxDynamicSharedMemorySize, SMEM_DYN);

    // 1: W hi/lo split + zero counts
    dim3 wgrid(64, 6);
    wsplit_zero_kernel<<<wgrid, 256>>>(WA, WB, WC, WD, WE, N);
    // 2: histogram
    hist_kernel<<<(E + 255) / 256, 256>>>(dst, E);
    // 3: per-chunk scan
    int nchunks = (N + 511) / 512;
    scan1_kernel<<<nchunks, 512>>>(N);
    // 4: node GEMMs
    dim3 ngrid((N + 63) / 64, 4);
    node_gemm_kernel<<<ngrid, 256, SMEM_DYN>>>(h, bA, bB, bD, bE, N);
    // 5: finish scan (prefix of chunks folded in)
    scan3_kernel<<<nchunks, 512>>>(N);
    // 6: fused edge GEMM + epilogue + sigma scatter
    edge_kernel<<<(E + 63) / 64, 256, SMEM_DYN>>>(e, src, dst, bC, e_out, E);
    // 7: segment sums + node update
    aggregate_kernel<<<(N + 3) / 4, 256>>>(h, h_out, N);
}

// round 11
// speedup vs baseline: 1.2746x; 1.1637x over previous
#include <cuda_runtime.h>
#include <cuda_bf16.h>
#include <cuda_fp16.h>
#include <cstdint>

#define D 128

static constexpr int MAXN = 50000;
static constexpr int MAXE = 600000;

// Scratch (allocation-free: __device__ globals)
__device__ float g_Ah[MAXN * D];
__device__ float g_Bh[MAXN * D];
__device__ float g_Dh[MAXN * D];
__device__ float g_Eh[MAXN * D];
__device__ __half g_sig[(size_t)MAXE * D];  // sigma rows, dst-sorted, fp16
__device__ int   g_srcs[MAXE];              // src per sorted slot
__device__ int   g_cnt[MAXN];
__device__ int   g_off[MAXN];
__device__ int   g_run[MAXN];
__device__ int   g_chunk[256];
__device__ __nv_bfloat16 g_Whi[5][128 * 128];  // order: A,B,C,D,E (row-major [n][k])
__device__ __nv_bfloat16 g_Wlo[5][128 * 128];

// ---------------------------------------------------------------------------
// SMEM: [align 1024] Whi(32K) Wlo(32K) Ahi(16K) Alo(16K) ctrl(1K)  => ~98K, 2 CTA/SM
// Edge: C fp32 tile (32K) overwrites the W region after MMA (A tiles preserved
// for e reconstruction). Node: direct fragment epilogue, no C tile at all.
// ---------------------------------------------------------------------------
#define OFF_WHI 0
#define OFF_WLO 32768
#define OFF_AHI 65536
#define OFF_ALO 81920
#define OFF_CE  0
#define OFF_CTRL 98304
#define SMEM_DYN (1024 + 98304 + 1024)

__device__ __forceinline__ uint32_t smem_u32(const void* p) {
    uint32_t a;
    asm("{ .reg .u64 t; cvta.to.shared.u64 t, %1; cvt.u32.u64 %0, t; }" : "=r"(a) : "l"(p));
    return a;
}

// bf16 tile swizzle: row-major, 256B rows, 16B-atom XOR swizzle
__device__ __forceinline__ uint32_t sw256(int r, int cbyte) {
    uint32_t o = (uint32_t)r * 256u + (uint32_t)cbyte;
    return o ^ (((uint32_t)r & 7u) << 4);
}
// fp32 C tile swizzle: 512B rows
__device__ __forceinline__ uint32_t sw512(int r, int cbyte) {
    uint32_t o = (uint32_t)r * 512u + (uint32_t)cbyte;
    return o ^ (((uint32_t)r & 7u) << 4);
}

__device__ __forceinline__ void cpasync16(uint32_t dst, const void* src) {
    asm volatile("cp.async.cg.shared.global [%0], [%1], 16;" :: "r"(dst), "l"(src));
}
#define CPASYNC_COMMIT() asm volatile("cp.async.commit_group;" ::: "memory")
#define CPASYNC_WAIT0()  asm volatile("cp.async.wait_group 0;" ::: "memory")

__device__ __forceinline__ void ldm4(uint32_t addr, uint32_t r[4]) {
    asm volatile("ldmatrix.sync.aligned.m8n8.x4.shared.b16 {%0,%1,%2,%3}, [%4];"
                 : "=r"(r[0]), "=r"(r[1]), "=r"(r[2]), "=r"(r[3]) : "r"(addr));
}

__device__ __forceinline__ void mma16816(float c[4], const uint32_t a[4],
                                         uint32_t b0, uint32_t b1) {
    asm volatile("mma.sync.aligned.m16n8k16.row.col.f32.bf16.bf16.f32 "
                 "{%0,%1,%2,%3}, {%4,%5,%6,%7}, {%8,%9}, {%0,%1,%2,%3};"
                 : "+f"(c[0]), "+f"(c[1]), "+f"(c[2]), "+f"(c[3])
                 : "r"(a[0]), "r"(a[1]), "r"(a[2]), "r"(a[3]), "r"(b0), "r"(b1));
}

__device__ __forceinline__ uint32_t pack_bf2(float x, float y) {
    __nv_bfloat162 t = __floats2bfloat162_rn(x, y);
    return *reinterpret_cast<uint32_t*>(&t);
}

__device__ __forceinline__ float2 unpack_bf2(uint32_t u) {
    __nv_bfloat162 t = *reinterpret_cast<__nv_bfloat162*>(&u);
    return make_float2(__bfloat162float(t.x), __bfloat162float(t.y));
}

// ---------------------------------------------------------------------------
// Fused W-split (5 weights) + zero counts
// ---------------------------------------------------------------------------
__global__ void wsplit_zero_kernel(const float* __restrict__ WA, const float* __restrict__ WB,
                                   const float* __restrict__ WC, const float* __restrict__ WD,
                                   const float* __restrict__ WE, int Nn) {
    if (blockIdx.y < 5) {
        const float* Ws[5] = {WA, WB, WC, WD, WE};
        int w = blockIdx.y;
        int i = blockIdx.x * 256 + threadIdx.x;
        float v = Ws[w][i];
        __nv_bfloat16 hi = __float2bfloat16(v);
        g_Whi[w][i] = hi;
        g_Wlo[w][i] = __float2bfloat16(v - __bfloat162float(hi));
    } else {
        for (int i = blockIdx.x * 256 + threadIdx.x; i < Nn; i += 64 * 256)
            g_cnt[i] = 0;
    }
}

// Copy pre-split W (bf16 row-major [128][128]) into swizzled smem via cp.async.
__device__ __forceinline__ void copy_w(uint32_t AL, const __nv_bfloat16* Whi,
                                       const __nv_bfloat16* Wlo, int tid) {
    for (int q = tid; q < 2048; q += 256) {
        int r = q >> 4;
        int cb = (q & 15) * 16;
        cpasync16(AL + OFF_WHI + sw256(r, cb), (const char*)Whi + r * 256 + cb);
        cpasync16(AL + OFF_WLO + sw256(r, cb), (const char*)Wlo + r * 256 + cb);
    }
    CPASYNC_COMMIT();
}

// Load a [64 x 128] fp32 tile -> hi/lo bf16 swizzled smem (8B STS).
// thread t: row t>>2, cols (t&3)*32 .. +31.
__device__ __forceinline__ void load_tile_hilo(char* lbase, const float* __restrict__ srcp,
                                               int row0, int cnt, int tid) {
    int r = tid >> 2;
    int c0 = (tid & 3) * 32;
    int grow = row0 + r;
    const float4* rowp = (const float4*)(srcp + (size_t)grow * D);
#pragma unroll
    for (int i = 0; i < 8; ++i) {
        int k = c0 + i * 4;
        float4 v = (grow < cnt) ? rowp[k >> 2] : make_float4(0.f, 0.f, 0.f, 0.f);
        __nv_bfloat16 h0 = __float2bfloat16(v.x);
        __nv_bfloat16 h1 = __float2bfloat16(v.y);
        __nv_bfloat16 h2 = __float2bfloat16(v.z);
        __nv_bfloat16 h3 = __float2bfloat16(v.w);
        uint32_t hi01 = pack_bf2(v.x, v.y);
        uint32_t hi23 = pack_bf2(v.z, v.w);
        uint32_t lo01 = pack_bf2(v.x - __bfloat162float(h0), v.y - __bfloat162float(h1));
        uint32_t lo23 = pack_bf2(v.z - __bfloat162float(h2), v.w - __bfloat162float(h3));
        uint32_t o = sw256(r, k * 2);
        *(uint2*)(lbase + OFF_AHI + o) = make_uint2(hi01, hi23);
        *(uint2*)(lbase + OFF_ALO + o) = make_uint2(lo01, lo23);
    }
}

// ---------------------------------------------------------------------------
// MMA mainloop: C[64,128] = A @ W^T, 3-term bf16 split.
// Warp w: rows (w&1)*32 (2 m-tiles), cols (w>>1)*32 (2 B-tiles = 4 n8).
// ---------------------------------------------------------------------------
__device__ __forceinline__ void gemm_mma(uint32_t AL, int tid, float acc[2][2][2][4]) {
    int lane = tid & 31, wid = tid >> 5;
    int mtb = (wid & 1) * 32;
    int ntb = (wid >> 1) * 32;
    int lrow = lane & 15;
    int lkoff = (lane >> 4) * 16;

#pragma unroll
    for (int kc = 0; kc < 8; ++kc) {
        int kb = kc * 32;
        uint32_t ah[2][4], al[2][4], bh[2][4], bl[2][4];
#pragma unroll
        for (int mt = 0; mt < 2; ++mt) {
            uint32_t so = sw256(mtb + mt * 16 + lrow, kb + lkoff);
            ldm4(AL + OFF_AHI + so, ah[mt]);
            ldm4(AL + OFF_ALO + so, al[mt]);
        }
#pragma unroll
        for (int nt = 0; nt < 2; ++nt) {
            uint32_t so = sw256(ntb + nt * 16 + lrow, kb + lkoff);
            ldm4(AL + OFF_WHI + so, bh[nt]);
            ldm4(AL + OFF_WLO + so, bl[nt]);
        }
#pragma unroll
        for (int mt = 0; mt < 2; ++mt)
#pragma unroll
            for (int nt = 0; nt < 2; ++nt)
#pragma unroll
                for (int q = 0; q < 2; ++q) {
                    float* c = acc[mt][nt][q];
                    mma16816(c, ah[mt], bh[nt][q], bh[nt][q + 2]);
                    mma16816(c, ah[mt], bl[nt][q], bl[nt][q + 2]);
                    mma16816(c, al[mt], bh[nt][q], bh[nt][q + 2]);
                }
    }
}

// Write accumulators into the fp32 C smem tile at byte offset coff.
__device__ __forceinline__ void store_c(char* lbase, int coff, int tid, float acc[2][2][2][4]) {
    int lane = tid & 31, wid = tid >> 5;
    int mtb = (wid & 1) * 32;
    int ntb = (wid >> 1) * 32;
#pragma unroll
    for (int mt = 0; mt < 2; ++mt)
#pragma unroll
        for (int nt = 0; nt < 2; ++nt)
#pragma unroll
            for (int q = 0; q < 2; ++q) {
                int r0 = mtb + mt * 16 + (lane >> 2);
                int cb = (ntb + nt * 16 + q * 8 + (lane & 3) * 2) * 4;
                float* c = acc[mt][nt][q];
                *(float2*)(lbase + coff + sw512(r0, cb))     = make_float2(c[0], c[1]);
                *(float2*)(lbase + coff + sw512(r0 + 8, cb)) = make_float2(c[2], c[3]);
            }
}

// ---------------------------------------------------------------------------
// Counting sort by dst (scan2 folded into scan3)
// ---------------------------------------------------------------------------
__global__ void hist_kernel(const int* __restrict__ dst, int Ecnt) {
    int i = blockIdx.x * blockDim.x + threadIdx.x;
    if (i < Ecnt) atomicAdd(&g_cnt[dst[i]], 1);
}
__global__ void scan1_kernel(int n) {
    __shared__ int sm[512];
    int tid = threadIdx.x;
    int i = blockIdx.x * 512 + tid;
    int v = (i < n) ? g_cnt[i] : 0;
    sm[tid] = v;
    __syncthreads();
    for (int off = 1; off < 512; off <<= 1) {
        int t = (tid >= off) ? sm[tid - off] : 0;
        __syncthreads();
        sm[tid] += t;
        __syncthreads();
    }
    if (i < n) g_off[i] = sm[tid] - v;
    if (tid == 511) g_chunk[blockIdx.x] = sm[511];
}
__global__ void scan3_kernel(int n) {
    __shared__ int pre;
    if (threadIdx.x == 0) {
        int acc = 0;
        for (int j = 0; j < blockIdx.x; ++j) acc += g_chunk[j];
        pre = acc;
    }
    __syncthreads();
    int i = blockIdx.x * 512 + threadIdx.x;
    if (i < n) {
        int o = g_off[i] + pre;
        g_off[i] = o;
        g_run[i] = o;
    }
}

// ---------------------------------------------------------------------------
// Node GEMMs: out = h @ W^T + b; direct fragment->gmem epilogue (no C smem)
// ---------------------------------------------------------------------------
__global__ __launch_bounds__(256, 2) void node_gemm_kernel(
    const float* __restrict__ h,
    const float* __restrict__ b0, const float* __restrict__ b1,
    const float* __restrict__ b2, const float* __restrict__ b3,
    int Nn) {
    extern __shared__ char smem[];
    uint32_t sbase = smem_u32(smem);
    uint32_t AL = (sbase + 1023) & ~1023u;
    char* lbase = smem + (AL - sbase);

    int which = blockIdx.y;
    int widx          = (which == 0) ? 0 : (which == 1) ? 1 : (which == 2) ? 3 : 4;
    const float* bias = (which == 0) ? b0 : (which == 1) ? b1 : (which == 2) ? b2 : b3;
    float* out        = (which == 0) ? g_Ah : (which == 1) ? g_Bh : (which == 2) ? g_Dh : g_Eh;

    int tid = threadIdx.x;
    int row0 = blockIdx.x * 64;

    copy_w(AL, g_Whi[widx], g_Wlo[widx], tid);
    load_tile_hilo(lbase, h, row0, Nn, tid);
    CPASYNC_WAIT0();
    __syncthreads();

    float acc[2][2][2][4] = {};
    gemm_mma(AL, tid, acc);

    // direct epilogue from fragments
    int lane = tid & 31, wid = tid >> 5;
    int mtb = (wid & 1) * 32;
    int ntb = (wid >> 1) * 32;
#pragma unroll
    for (int mt = 0; mt < 2; ++mt)
#pragma unroll
        for (int nt = 0; nt < 2; ++nt)
#pragma unroll
            for (int q = 0; q < 2; ++q) {
                int r0 = row0 + mtb + mt * 16 + (lane >> 2);
                int col = ntb + nt * 16 + q * 8 + (lane & 3) * 2;
                float2 b2v = *(const float2*)(bias + col);
                float* c = acc[mt][nt][q];
                if (r0 < Nn)
                    *(float2*)(out + (size_t)r0 * D + col) =
                        make_float2(c[0] + b2v.x, c[1] + b2v.y);
                if (r0 + 8 < Nn)
                    *(float2*)(out + (size_t)(r0 + 8) * D + col) =
                        make_float2(c[2] + b2v.x, c[3] + b2v.y);
            }
}

// ---------------------------------------------------------------------------
// Fused edge kernel (64 edges per block, 2 CTA/SM):
// Ce GEMM + gather(Dh[src],Eh[dst]) + sigmoid + e_out + fp16 sigma scatter.
// Slot-claim atomic issued BEFORE the mainloop (latency hidden under MMAs);
// C tile goes over the dead W region so A hi/lo survive for e reconstruction.
// ---------------------------------------------------------------------------
__global__ __launch_bounds__(256, 2) void edge_kernel(
    const float* __restrict__ e,
    const int* __restrict__ src, const int* __restrict__ dst,
    const float* __restrict__ bC,
    float* __restrict__ e_out, int Ecnt) {
    extern __shared__ char smem[];
    uint32_t sbase = smem_u32(smem);
    uint32_t AL = (sbase + 1023) & ~1023u;
    char* lbase = smem + (AL - sbase);

    int tid = threadIdx.x;
    int lane = tid & 31;
    int m0 = blockIdx.x * 64;

    int* sSrc = (int*)(lbase + OFF_CTRL);
    int* sDst = (int*)(lbase + OFF_CTRL + 256);

    copy_w(AL, g_Whi[2], g_Wlo[2], tid);
    load_tile_hilo(lbase, e, m0, Ecnt, tid);
    if (tid < 64) {
        int m = m0 + tid;
        sSrc[tid] = (m < Ecnt) ? src[m] : 0;
        sDst[tid] = (m < Ecnt) ? dst[m] : 0;
    }
    CPASYNC_WAIT0();
    __syncthreads();

    // claim dst-sorted slot early; atomic latency hides under the mainloop
    int r = tid >> 2;
    int ch = tid & 3;
    int m = m0 + r;
    int p = 0;
    if (ch == 0 && m < Ecnt) {
        int dd = sDst[r];
        p = atomicAdd(&g_run[dd], 1);
        g_srcs[p] = sSrc[r];
    }

    float acc[2][2][2][4] = {};
    gemm_mma(AL, tid, acc);
    __syncthreads();   // W fragment reads done before C overwrites W region
    store_c(lbase, OFF_CE, tid, acc);
    __syncthreads();   // C visible

    if (m < Ecnt) {
        int dd = sDst[r];
        int pos = __shfl_sync(0xffffffffu, p, lane & ~3);
        const float* DhS = g_Dh + (size_t)sSrc[r] * D;
        const float* EhD = g_Eh + (size_t)dd * D;
        float* eo = e_out + (size_t)m * D;
        __half2* sigRow = (__half2*)(g_sig + (size_t)pos * D);
#pragma unroll
        for (int i = 0; i < 8; ++i) {
            int col = ch * 32 + i * 4;
            float4 c4 = *(const float4*)(lbase + OFF_CE + sw512(r, col * 4));
            float4 b4 = *(const float4*)(bC + col);
            float4 dh = *(const float4*)(DhS + col);
            float4 eh = *(const float4*)(EhD + col);
            // reconstruct e = hi + lo from preserved A smem tiles
            uint2 hu = *(const uint2*)(lbase + OFF_AHI + sw256(r, col * 2));
            uint2 lu = *(const uint2*)(lbase + OFF_ALO + sw256(r, col * 2));
            float2 h01 = unpack_bf2(hu.x), h23 = unpack_bf2(hu.y);
            float2 l01 = unpack_bf2(lu.x), l23 = unpack_bf2(lu.y);
            float e0 = h01.x + l01.x, e1 = h01.y + l01.y;
            float e2 = h23.x + l23.x, e3 = h23.y + l23.y;

            float x0 = c4.x + b4.x + dh.x + eh.x;
            float x1 = c4.y + b4.y + dh.y + eh.y;
            float x2 = c4.z + b4.z + dh.z + eh.z;
            float x3 = c4.w + b4.w + dh.w + eh.w;
            float s0 = 1.f / (1.f + __expf(-x0));
            float s1 = 1.f / (1.f + __expf(-x1));
            float s2 = 1.f / (1.f + __expf(-x2));
            float s3 = 1.f / (1.f + __expf(-x3));
            *(float4*)(eo + col) = make_float4(e0 + x0 * s0, e1 + x1 * s1,
                                               e2 + x2 * s2, e3 + x3 * s3);
            sigRow[col >> 1]       = __floats2half2_rn(s0, s1);
            sigRow[(col >> 1) + 1] = __floats2half2_rn(s2, s3);
        }
    }
}

// ---------------------------------------------------------------------------
// Aggregate (vectorized, 2x unrolled for MLP): per-node segment sums + node_final
// ---------------------------------------------------------------------------
__global__ __launch_bounds__(256) void aggregate_kernel(
    const float* __restrict__ h, float* __restrict__ h_out, int Nn) {
    int node = blockIdx.x * 4 + (threadIdx.x >> 6);
    int j2 = threadIdx.x & 63;   // column-pair index
    if (node >= Nn) return;

    int off = g_off[node];
    int cnt = g_cnt[node];
    const __half2* sig2 = (const __half2*)g_sig;
    float ss0 = 0.f, ss1 = 0.f, sm0 = 0.f, sm1 = 0.f;
    float ts0 = 0.f, ts1 = 0.f, tm0 = 0.f, tm1 = 0.f;
    int i = 0;
    for (; i + 2 <= cnt; i += 2) {
        size_t ba = (size_t)(off + i), bb = ba + 1;
        float2 sga = __half22float2(sig2[ba * 64 + j2]);
        float2 sgb = __half22float2(sig2[bb * 64 + j2]);
        int sa = g_srcs[off + i];
        int sb = g_srcs[off + i + 1];
        float2 bha = *(const float2*)(g_Bh + (size_t)sa * D + j2 * 2);
        float2 bhb = *(const float2*)(g_Bh + (size_t)sb * D + j2 * 2);
        sm0 += bha.x * sga.x; sm1 += bha.y * sga.y;
        tm0 += bhb.x * sgb.x; tm1 += bhb.y * sgb.y;
        ss0 += sga.x; ss1 += sga.y;
        ts0 += sgb.x; ts1 += sgb.y;
    }
    if (i < cnt) {
        float2 sg = __half22float2(sig2[(size_t)(off + i) * 64 + j2]);
        int s = g_srcs[off + i];
        float2 bh = *(const float2*)(g_Bh + (size_t)s * D + j2 * 2);
        sm0 += bh.x * sg.x; sm1 += bh.y * sg.y;
        ss0 += sg.x; ss1 += sg.y;
    }
    sm0 += tm0; sm1 += tm1; ss0 += ts0; ss1 += ts1;

    float2 ah = *(const float2*)(g_Ah + (size_t)node * D + j2 * 2);
    float x0 = ah.x + sm0 / (ss0 + 1e-6f);
    float x1 = ah.y + sm1 / (ss1 + 1e-6f);
    float g0 = 1.f / (1.f + __expf(-x0));
    float g1 = 1.f / (1.f + __expf(-x1));
    float2 hv = *(const float2*)(h + (size_t)node * D + j2 * 2);
    *(float2*)(h_out + (size_t)node * D + j2 * 2) =
        make_float2(hv.x + x0 * g0, hv.y + x1 * g1);
}

extern "C" void kernel_launch(void* const* d_in, const int* in_sizes, int n_in,
                              void* d_out, int out_size) {
    const float* h   = (const float*)d_in[0];
    const float* e   = (const float*)d_in[1];
    const int*   src = (const int*)d_in[2];
    const int*   dst = (const int*)d_in[3];
    const float* WA = (const float*)d_in[4];  const float* bA = (const float*)d_in[5];
    const float* WB = (const float*)d_in[6];  const float* bB = (const float*)d_in[7];
    const float* WC = (const float*)d_in[8];  const float* bC = (const float*)d_in[9];
    const float* WD = (const float*)d_in[10]; const float* bD = (const float*)d_in[11];
    const float* WE = (const float*)d_in[12]; const float* bE = (const float*)d_in[13];

    int N = in_sizes[0] / D;
    int E = in_sizes[2];

    float* out   = (float*)d_out;
    float* h_out = out;
    float* e_out = out + (size_t)N * D;

    cudaFuncSetAttribute(node_gemm_kernel, cudaFuncAttributeMaxDynamicSharedMemorySize, SMEM_DYN);
    cudaFuncSetAttribute(edge_kernel,      cudaFuncAttributeMaxDynamicSharedMemorySize, SMEM_DYN);

    // 1: W hi/lo split + zero counts
    dim3 wgrid(64, 6);
    wsplit_zero_kernel<<<wgrid, 256>>>(WA, WB, WC, WD, WE, N);
    // 2: histogram
    hist_kernel<<<(E + 255) / 256, 256>>>(dst, E);
    // 3: per-chunk scan
    int nchunks = (N + 511) / 512;
    scan1_kernel<<<nchunks, 512>>>(N);
    // 4: node GEMMs
    dim3 ngrid((N + 63) / 64, 4);
    node_gemm_kernel<<<ngrid, 256, SMEM_DYN>>>(h, bA, bB, bD, bE, N);
    // 5: finish scan (prefix of chunks folded in)
    scan3_kernel<<<nchunks, 512>>>(N);
    // 6: fused edge GEMM + epilogue + sigma scatter
    edge_kernel<<<(E + 63) / 64, 256, SMEM_DYN>>>(e, src, dst, bC, e_out, E);
    // 7: segment sums + node update
    aggregate_kernel<<<(N + 3) / 4, 256>>>(h, h_out, N);
}

// round 15
// speedup vs baseline: 1.8043x; 1.4156x over previous
#include <cuda_runtime.h>
#include <cuda_bf16.h>
#include <cuda_fp16.h>
#include <cstdint>

#define D 128

static constexpr int MAXN = 50000;
static constexpr int MAXE = 600000;

// Scratch (allocation-free: __device__ globals)
__device__ float g_Ah[MAXN * D];
__device__ float g_Bh[MAXN * D];
__device__ float g_Dh[MAXN * D];
__device__ float g_Eh[MAXN * D];
__device__ __half g_sig[(size_t)MAXE * D];  // sigma rows, dst-sorted, fp16
__device__ int   g_srcs[MAXE];              // src per sorted slot
__device__ int   g_cnt[MAXN];
__device__ int   g_off[MAXN];
__device__ int   g_run[MAXN];
__device__ int   g_chunk[256];
__device__ __nv_bfloat16 g_Whi[5][128 * 128];  // order: A,B,C,D,E (row-major [n][k])
__device__ __nv_bfloat16 g_Wlo[5][128 * 128];

// ---------------------------------------------------------------------------
// SMEM: [align 1024] Whi(32K) Wlo(32K) Ahi(16K) Alo(16K) ctrl(1K)  => ~98K, 2 CTA/SM
// No C tile anywhere: node and edge both do direct fragment epilogues.
// ---------------------------------------------------------------------------
#define OFF_WHI 0
#define OFF_WLO 32768
#define OFF_AHI 65536
#define OFF_ALO 81920
#define OFF_CTRL 98304
#define SMEM_DYN (1024 + 98304 + 1024)

__device__ __forceinline__ uint32_t smem_u32(const void* p) {
    uint32_t a;
    asm("{ .reg .u64 t; cvta.to.shared.u64 t, %1; cvt.u32.u64 %0, t; }" : "=r"(a) : "l"(p));
    return a;
}

// bf16 tile swizzle: row-major, 256B rows, 16B-atom XOR swizzle
__device__ __forceinline__ uint32_t sw256(int r, int cbyte) {
    uint32_t o = (uint32_t)r * 256u + (uint32_t)cbyte;
    return o ^ (((uint32_t)r & 7u) << 4);
}

__device__ __forceinline__ void cpasync16(uint32_t dst, const void* src) {
    asm volatile("cp.async.cg.shared.global [%0], [%1], 16;" :: "r"(dst), "l"(src));
}
#define CPASYNC_COMMIT() asm volatile("cp.async.commit_group;" ::: "memory")
#define CPASYNC_WAIT0()  asm volatile("cp.async.wait_group 0;" ::: "memory")

__device__ __forceinline__ void ldm4(uint32_t addr, uint32_t r[4]) {
    asm volatile("ldmatrix.sync.aligned.m8n8.x4.shared.b16 {%0,%1,%2,%3}, [%4];"
                 : "=r"(r[0]), "=r"(r[1]), "=r"(r[2]), "=r"(r[3]) : "r"(addr));
}

__device__ __forceinline__ void mma16816(float c[4], const uint32_t a[4],
                                         uint32_t b0, uint32_t b1) {
    asm volatile("mma.sync.aligned.m16n8k16.row.col.f32.bf16.bf16.f32 "
                 "{%0,%1,%2,%3}, {%4,%5,%6,%7}, {%8,%9}, {%0,%1,%2,%3};"
                 : "+f"(c[0]), "+f"(c[1]), "+f"(c[2]), "+f"(c[3])
                 : "r"(a[0]), "r"(a[1]), "r"(a[2]), "r"(a[3]), "r"(b0), "r"(b1));
}

__device__ __forceinline__ uint32_t pack_bf2(float x, float y) {
    __nv_bfloat162 t = __floats2bfloat162_rn(x, y);
    return *reinterpret_cast<uint32_t*>(&t);
}

__device__ __forceinline__ float2 unpack_bf2(uint32_t u) {
    __nv_bfloat162 t = *reinterpret_cast<__nv_bfloat162*>(&u);
    return make_float2(__bfloat162float(t.x), __bfloat162float(t.y));
}

// ---------------------------------------------------------------------------
// Fused W-split (5 weights) + zero counts
// ---------------------------------------------------------------------------
__global__ void wsplit_zero_kernel(const float* __restrict__ WA, const float* __restrict__ WB,
                                   const float* __restrict__ WC, const float* __restrict__ WD,
                                   const float* __restrict__ WE, int Nn) {
    if (blockIdx.y < 5) {
        const float* Ws[5] = {WA, WB, WC, WD, WE};
        int w = blockIdx.y;
        int i = blockIdx.x * 256 + threadIdx.x;
        float v = Ws[w][i];
        __nv_bfloat16 hi = __float2bfloat16(v);
        g_Whi[w][i] = hi;
        g_Wlo[w][i] = __float2bfloat16(v - __bfloat162float(hi));
    } else {
        for (int i = blockIdx.x * 256 + threadIdx.x; i < Nn; i += 64 * 256)
            g_cnt[i] = 0;
    }
}

// Copy pre-split W (bf16 row-major [128][128]) into swizzled smem via cp.async.
__device__ __forceinline__ void copy_w(uint32_t AL, const __nv_bfloat16* Whi,
                                       const __nv_bfloat16* Wlo, int tid) {
    for (int q = tid; q < 2048; q += 256) {
        int r = q >> 4;
        int cb = (q & 15) * 16;
        cpasync16(AL + OFF_WHI + sw256(r, cb), (const char*)Whi + r * 256 + cb);
        cpasync16(AL + OFF_WLO + sw256(r, cb), (const char*)Wlo + r * 256 + cb);
    }
    CPASYNC_COMMIT();
}

// Load a [64 x 128] fp32 tile -> hi/lo bf16 swizzled smem (8B STS).
// thread t: row t>>2, cols (t&3)*32 .. +31.
__device__ __forceinline__ void load_tile_hilo(char* lbase, const float* __restrict__ srcp,
                                               int row0, int cnt, int tid) {
    int r = tid >> 2;
    int c0 = (tid & 3) * 32;
    int grow = row0 + r;
    const float4* rowp = (const float4*)(srcp + (size_t)grow * D);
#pragma unroll
    for (int i = 0; i < 8; ++i) {
        int k = c0 + i * 4;
        float4 v = (grow < cnt) ? rowp[k >> 2] : make_float4(0.f, 0.f, 0.f, 0.f);
        __nv_bfloat16 h0 = __float2bfloat16(v.x);
        __nv_bfloat16 h1 = __float2bfloat16(v.y);
        __nv_bfloat16 h2 = __float2bfloat16(v.z);
        __nv_bfloat16 h3 = __float2bfloat16(v.w);
        uint32_t hi01 = pack_bf2(v.x, v.y);
        uint32_t hi23 = pack_bf2(v.z, v.w);
        uint32_t lo01 = pack_bf2(v.x - __bfloat162float(h0), v.y - __bfloat162float(h1));
        uint32_t lo23 = pack_bf2(v.z - __bfloat162float(h2), v.w - __bfloat162float(h3));
        uint32_t o = sw256(r, k * 2);
        *(uint2*)(lbase + OFF_AHI + o) = make_uint2(hi01, hi23);
        *(uint2*)(lbase + OFF_ALO + o) = make_uint2(lo01, lo23);
    }
}

// ---------------------------------------------------------------------------
// MMA mainloop: C[64,128] += A @ W^T, 3-term bf16 split (acc NOT zeroed here).
// Warp w: rows (w&1)*32 (2 m-tiles), cols (w>>1)*32 (2 B-tiles = 4 n8).
// ---------------------------------------------------------------------------
__device__ __forceinline__ void gemm_mma(uint32_t AL, int tid, float acc[2][2][2][4]) {
    int lane = tid & 31, wid = tid >> 5;
    int mtb = (wid & 1) * 32;
    int ntb = (wid >> 1) * 32;
    int lrow = lane & 15;
    int lkoff = (lane >> 4) * 16;

#pragma unroll
    for (int kc = 0; kc < 8; ++kc) {
        int kb = kc * 32;
        uint32_t ah[2][4], al[2][4], bh[2][4], bl[2][4];
#pragma unroll
        for (int mt = 0; mt < 2; ++mt) {
            uint32_t so = sw256(mtb + mt * 16 + lrow, kb + lkoff);
            ldm4(AL + OFF_AHI + so, ah[mt]);
            ldm4(AL + OFF_ALO + so, al[mt]);
        }
#pragma unroll
        for (int nt = 0; nt < 2; ++nt) {
            uint32_t so = sw256(ntb + nt * 16 + lrow, kb + lkoff);
            ldm4(AL + OFF_WHI + so, bh[nt]);
            ldm4(AL + OFF_WLO + so, bl[nt]);
        }
#pragma unroll
        for (int mt = 0; mt < 2; ++mt)
#pragma unroll
            for (int nt = 0; nt < 2; ++nt)
#pragma unroll
                for (int q = 0; q < 2; ++q) {
                    float* c = acc[mt][nt][q];
                    mma16816(c, ah[mt], bh[nt][q], bh[nt][q + 2]);
                    mma16816(c, ah[mt], bl[nt][q], bl[nt][q + 2]);
                    mma16816(c, al[mt], bh[nt][q], bh[nt][q + 2]);
                }
    }
}

// ---------------------------------------------------------------------------
// Counting sort by dst (scan2 folded into scan3)
// ---------------------------------------------------------------------------
__global__ void hist_kernel(const int* __restrict__ dst, int Ecnt) {
    int i = blockIdx.x * blockDim.x + threadIdx.x;
    if (i < Ecnt) atomicAdd(&g_cnt[dst[i]], 1);
}
__global__ void scan1_kernel(int n) {
    __shared__ int sm[512];
    int tid = threadIdx.x;
    int i = blockIdx.x * 512 + tid;
    int v = (i < n) ? g_cnt[i] : 0;
    sm[tid] = v;
    __syncthreads();
    for (int off = 1; off < 512; off <<= 1) {
        int t = (tid >= off) ? sm[tid - off] : 0;
        __syncthreads();
        sm[tid] += t;
        __syncthreads();
    }
    if (i < n) g_off[i] = sm[tid] - v;
    if (tid == 511) g_chunk[blockIdx.x] = sm[511];
}
__global__ void scan3_kernel(int n) {
    __shared__ int pre;
    if (threadIdx.x == 0) {
        int acc = 0;
        for (int j = 0; j < blockIdx.x; ++j) acc += g_chunk[j];
        pre = acc;
    }
    __syncthreads();
    int i = blockIdx.x * 512 + threadIdx.x;
    if (i < n) {
        int o = g_off[i] + pre;
        g_off[i] = o;
        g_run[i] = o;
    }
}

// ---------------------------------------------------------------------------
// Node GEMMs: ONE A-load, FOUR GEMMs (W A/B/D/E cycled through smem).
// Direct fragment->gmem epilogue; next W prefetched during epilogue.
// ---------------------------------------------------------------------------
__global__ __launch_bounds__(256, 2) void node_gemm_kernel(
    const float* __restrict__ h,
    const float* __restrict__ b0, const float* __restrict__ b1,
    const float* __restrict__ b2, const float* __restrict__ b3,
    int Nn) {
    extern __shared__ char smem[];
    uint32_t sbase = smem_u32(smem);
    uint32_t AL = (sbase + 1023) & ~1023u;
    char* lbase = smem + (AL - sbase);

    const __nv_bfloat16* whis[4] = {g_Whi[0], g_Whi[1], g_Whi[3], g_Whi[4]};
    const __nv_bfloat16* wlos[4] = {g_Wlo[0], g_Wlo[1], g_Wlo[3], g_Wlo[4]};
    const float* bs[4] = {b0, b1, b2, b3};
    float* outs[4] = {g_Ah, g_Bh, g_Dh, g_Eh};

    int tid = threadIdx.x;
    int row0 = blockIdx.x * 64;
    int lane = tid & 31, wid = tid >> 5;
    int mtb = (wid & 1) * 32;
    int ntb = (wid >> 1) * 32;

    copy_w(AL, whis[0], wlos[0], tid);
    load_tile_hilo(lbase, h, row0, Nn, tid);
    CPASYNC_WAIT0();
    __syncthreads();

#pragma unroll
    for (int w = 0; w < 4; ++w) {
        float acc[2][2][2][4] = {};
        gemm_mma(AL, tid, acc);
        __syncthreads();                      // all warps done reading W[w]
        if (w < 3) copy_w(AL, whis[w + 1], wlos[w + 1], tid);  // overlaps epilogue

        const float* bias = bs[w];
        float* out = outs[w];
#pragma unroll
        for (int mt = 0; mt < 2; ++mt)
#pragma unroll
            for (int nt = 0; nt < 2; ++nt)
#pragma unroll
                for (int q = 0; q < 2; ++q) {
                    int r0 = row0 + mtb + mt * 16 + (lane >> 2);
                    int col = ntb + nt * 16 + q * 8 + (lane & 3) * 2;
                    float2 b2v = *(const float2*)(bias + col);
                    float* c = acc[mt][nt][q];
                    if (r0 < Nn)
                        *(float2*)(out + (size_t)r0 * D + col) =
                            make_float2(c[0] + b2v.x, c[1] + b2v.y);
                    if (r0 + 8 < Nn)
                        *(float2*)(out + (size_t)(r0 + 8) * D + col) =
                            make_float2(c[2] + b2v.x, c[3] + b2v.y);
                }
        if (w < 3) {
            CPASYNC_WAIT0();
            __syncthreads();
        }
    }
}

// ---------------------------------------------------------------------------
// Fused edge kernel (64 edges per block, 2 CTA/SM), accumulator-preloaded:
// acc = bC + Dh[src] + Eh[dst]  (gathers overlap the MMA mainloop),
// then acc += e @ WC^T, then sigmoid/e_out/sigma straight from fragments.
// No C smem tile, no post-mainloop syncs.
// ---------------------------------------------------------------------------
__global__ __launch_bounds__(256, 2) void edge_kernel(
    const float* __restrict__ e,
    const int* __restrict__ src, const int* __restrict__ dst,
    const float* __restrict__ bC,
    float* __restrict__ e_out, int Ecnt) {
    extern __shared__ char smem[];
    uint32_t sbase = smem_u32(smem);
    uint32_t AL = (sbase + 1023) & ~1023u;
    char* lbase = smem + (AL - sbase);

    int tid = threadIdx.x;
    int m0 = blockIdx.x * 64;

    int* sSrc = (int*)(lbase + OFF_CTRL);
    int* sDst = (int*)(lbase + OFF_CTRL + 256);
    int* sPos = (int*)(lbase + OFF_CTRL + 512);

    copy_w(AL, g_Whi[2], g_Wlo[2], tid);
    load_tile_hilo(lbase, e, m0, Ecnt, tid);
    if (tid < 64) {
        int m = m0 + tid;
        sSrc[tid] = (m < Ecnt) ? src[m] : 0;
        sDst[tid] = (m < Ecnt) ? dst[m] : 0;
    }
    CPASYNC_WAIT0();
    __syncthreads();

    // claim dst-sorted slots (atomic latency hides under preload+mainloop)
    int rr = tid >> 2;
    if ((tid & 3) == 0 && m0 + rr < Ecnt) {
        int dd = sDst[rr];
        int p = atomicAdd(&g_run[dd], 1);
        g_srcs[p] = sSrc[rr];
        sPos[rr] = p;
    }
    __syncthreads();   // sPos visible to fragment owners

    int lane = tid & 31, wid = tid >> 5;
    int mtb = (wid & 1) * 32;
    int ntb = (wid >> 1) * 32;

    // preload accumulators with bC + Dh[src] + Eh[dst]
    float acc[2][2][2][4];
#pragma unroll
    for (int mt = 0; mt < 2; ++mt) {
        int r0 = mtb + mt * 16 + (lane >> 2);
        int s0 = sSrc[r0], d0 = sDst[r0];
        int s1 = sSrc[r0 + 8], d1 = sDst[r0 + 8];
        const float* dh0p = g_Dh + (size_t)s0 * D;
        const float* eh0p = g_Eh + (size_t)d0 * D;
        const float* dh1p = g_Dh + (size_t)s1 * D;
        const float* eh1p = g_Eh + (size_t)d1 * D;
#pragma unroll
        for (int nt = 0; nt < 2; ++nt)
#pragma unroll
            for (int q = 0; q < 2; ++q) {
                int col = ntb + nt * 16 + q * 8 + (lane & 3) * 2;
                float2 bb = *(const float2*)(bC + col);
                float2 dh0 = *(const float2*)(dh0p + col);
                float2 eh0 = *(const float2*)(eh0p + col);
                float2 dh1 = *(const float2*)(dh1p + col);
                float2 eh1 = *(const float2*)(eh1p + col);
                float* c = acc[mt][nt][q];
                c[0] = bb.x + dh0.x + eh0.x;
                c[1] = bb.y + dh0.y + eh0.y;
                c[2] = bb.x + dh1.x + eh1.x;
                c[3] = bb.y + dh1.y + eh1.y;
            }
    }

    gemm_mma(AL, tid, acc);   // acc now holds x = e_new

    // epilogue straight from fragments; e reconstructed from preserved A tiles
#pragma unroll
    for (int mt = 0; mt < 2; ++mt) {
        int r0 = mtb + mt * 16 + (lane >> 2);
#pragma unroll
        for (int hh = 0; hh < 2; ++hh) {
            int row = r0 + hh * 8;
            int m = m0 + row;
            if (m >= Ecnt) continue;
            int pos = sPos[row];
            float* eo = e_out + (size_t)m * D;
            __half2* sigRow = (__half2*)(g_sig + (size_t)pos * D);
#pragma unroll
            for (int nt = 0; nt < 2; ++nt)
#pragma unroll
                for (int q = 0; q < 2; ++q) {
                    int col = ntb + nt * 16 + q * 8 + (lane & 3) * 2;
                    float x0 = acc[mt][nt][q][2 * hh];
                    float x1 = acc[mt][nt][q][2 * hh + 1];
                    uint32_t hu = *(const uint32_t*)(lbase + OFF_AHI + sw256(row, col * 2));
                    uint32_t lu = *(const uint32_t*)(lbase + OFF_ALO + sw256(row, col * 2));
                    float2 hv = unpack_bf2(hu);
                    float2 lv = unpack_bf2(lu);
                    float s0 = 1.f / (1.f + __expf(-x0));
                    float s1 = 1.f / (1.f + __expf(-x1));
                    *(float2*)(eo + col) = make_float2(hv.x + lv.x + x0 * s0,
                                                       hv.y + lv.y + x1 * s1);
                    sigRow[col >> 1] = __floats2half2_rn(s0, s1);
                }
        }
    }
}

// ---------------------------------------------------------------------------
// Aggregate (vectorized, 2x unrolled for MLP): per-node segment sums + node_final
// ---------------------------------------------------------------------------
__global__ __launch_bounds__(256) void aggregate_kernel(
    const float* __restrict__ h, float* __restrict__ h_out, int Nn) {
    int node = blockIdx.x * 4 + (threadIdx.x >> 6);
    int j2 = threadIdx.x & 63;   // column-pair index
    if (node >= Nn) return;

    int off = g_off[node];
    int cnt = g_cnt[node];
    const __half2* sig2 = (const __half2*)g_sig;
    float ss0 = 0.f, ss1 = 0.f, sm0 = 0.f, sm1 = 0.f;
    float ts0 = 0.f, ts1 = 0.f, tm0 = 0.f, tm1 = 0.f;
    int i = 0;
    for (; i + 2 <= cnt; i += 2) {
        size_t ba = (size_t)(off + i), bb = ba + 1;
        float2 sga = __half22float2(sig2[ba * 64 + j2]);
        float2 sgb = __half22float2(sig2[bb * 64 + j2]);
        int sa = g_srcs[off + i];
        int sb = g_srcs[off + i + 1];
        float2 bha = *(const float2*)(g_Bh + (size_t)sa * D + j2 * 2);
        float2 bhb = *(const float2*)(g_Bh + (size_t)sb * D + j2 * 2);
        sm0 += bha.x * sga.x; sm1 += bha.y * sga.y;
        tm0 += bhb.x * sgb.x; tm1 += bhb.y * sgb.y;
        ss0 += sga.x; ss1 += sga.y;
        ts0 += sgb.x; ts1 += sgb.y;
    }
    if (i < cnt) {
        float2 sg = __half22float2(sig2[(size_t)(off + i) * 64 + j2]);
        int s = g_srcs[off + i];
        float2 bh = *(const float2*)(g_Bh + (size_t)s * D + j2 * 2);
        sm0 += bh.x * sg.x; sm1 += bh.y * sg.y;
        ss0 += sg.x; ss1 += sg.y;
    }
    sm0 += tm0; sm1 += tm1; ss0 += ts0; ss1 += ts1;

    float2 ah = *(const float2*)(g_Ah + (size_t)node * D + j2 * 2);
    float x0 = ah.x + sm0 / (ss0 + 1e-6f);
    float x1 = ah.y + sm1 / (ss1 + 1e-6f);
    float g0 = 1.f / (1.f + __expf(-x0));
    float g1 = 1.f / (1.f + __expf(-x1));
    float2 hv = *(const float2*)(h + (size_t)node * D + j2 * 2);
    *(float2*)(h_out + (size_t)node * D + j2 * 2) =
        make_float2(hv.x + x0 * g0, hv.y + x1 * g1);
}

extern "C" void kernel_launch(void* const* d_in, const int* in_sizes, int n_in,
                              void* d_out, int out_size) {
    const float* h   = (const float*)d_in[0];
    const float* e   = (const float*)d_in[1];
    const int*   src = (const int*)d_in[2];
    const int*   dst = (const int*)d_in[3];
    const float* WA = (const float*)d_in[4];  const float* bA = (const float*)d_in[5];
    const float* WB = (const float*)d_in[6];  const float* bB = (const float*)d_in[7];
    const float* WC = (const float*)d_in[8];  const float* bC = (const float*)d_in[9];
    const float* WD = (const float*)d_in[10]; const float* bD = (const float*)d_in[11];
    const float* WE = (const float*)d_in[12]; const float* bE = (const float*)d_in[13];

    int N = in_sizes[0] / D;
    int E = in_sizes[2];

    float* out   = (float*)d_out;
    float* h_out = out;
    float* e_out = out + (size_t)N * D;

    cudaFuncSetAttribute(node_gemm_kernel, cudaFuncAttributeMaxDynamicSharedMemorySize, SMEM_DYN);
    cudaFuncSetAttribute(edge_kernel,      cudaFuncAttributeMaxDynamicSharedMemorySize, SMEM_DYN);

    // 1: W hi/lo split + zero counts
    dim3 wgrid(64, 6);
    wsplit_zero_kernel<<<wgrid, 256>>>(WA, WB, WC, WD, WE, N);
    // 2: histogram
    hist_kernel<<<(E + 255) / 256, 256>>>(dst, E);
    // 3: per-chunk scan
    int nchunks = (N + 511) / 512;
    scan1_kernel<<<nchunks, 512>>>(N);
    // 4: node GEMMs (one A-load, four GEMMs)
    node_gemm_kernel<<<(N + 63) / 64, 256, SMEM_DYN>>>(h, bA, bB, bD, bE, N);
    // 5: finish scan (prefix of chunks folded in)
    scan3_kernel<<<nchunks, 512>>>(N);
    // 6: fused edge GEMM + epilogue + sigma scatter
    edge_kernel<<<(E + 63) / 64, 256, SMEM_DYN>>>(e, src, dst, bC, e_out, E);
    // 7: segment sums + node update
    aggregate_kernel<<<(N + 3) / 4, 256>>>(h, h_out, N);
}